// round 9
// baseline (speedup 1.0000x reference)
#include <cuda_runtime.h>
#include <cuda_fp16.h>
#include <math.h>
#include <stdint.h>

#define T_TOK 2048
#define HID   2048
#define INTD  1024
#define NE    32
#define NE_TOT 33
#define TOPK  4
#define MAXTILES 128
#define BM    128
#define ROWS_MAX 10368

// ===================== device scratch =====================
__device__ int   g_cnt[NE_TOT];
__device__ int   g_tok[NE_TOT * T_TOK];
__device__ float g_w  [NE_TOT * T_TOK];
__device__ int   g_off[NE_TOT + 1];
__device__ int   g_tile_e[MAXTILES];
__device__ int   g_tile_s[MAXTILES];
__device__ int   g_ntiles;
__device__ __align__(16) __half g_hhi[(size_t)ROWS_MAX * INTD];
__device__ __align__(16) __half g_hlo[(size_t)ROWS_MAX * INTD];

// ===================== PTX helpers =====================
__device__ __forceinline__ uint32_t smem_u32(const void* p) {
    uint32_t a;
    asm("{ .reg .u64 t; cvta.to.shared.u64 t, %1; cvt.u32.u64 %0, t; }" : "=r"(a) : "l"(p));
    return a;
}
__device__ __forceinline__ void ldsm_x4(uint32_t* r, uint32_t a) {
    asm volatile("ldmatrix.sync.aligned.m8n8.x4.shared.b16 {%0,%1,%2,%3}, [%4];"
                 : "=r"(r[0]), "=r"(r[1]), "=r"(r[2]), "=r"(r[3]) : "r"(a));
}
__device__ __forceinline__ void ldsm_x4_t(uint32_t* r, uint32_t a) {
    asm volatile("ldmatrix.sync.aligned.m8n8.x4.trans.shared.b16 {%0,%1,%2,%3}, [%4];"
                 : "=r"(r[0]), "=r"(r[1]), "=r"(r[2]), "=r"(r[3]) : "r"(a));
}
__device__ __forceinline__ void mma_f16(float* c, const uint32_t* a, const uint32_t* b) {
    asm volatile("mma.sync.aligned.m16n8k16.row.col.f32.f16.f16.f32 "
        "{%0,%1,%2,%3}, {%4,%5,%6,%7}, {%8,%9}, {%0,%1,%2,%3};"
        : "+f"(c[0]), "+f"(c[1]), "+f"(c[2]), "+f"(c[3])
        : "r"(a[0]), "r"(a[1]), "r"(a[2]), "r"(a[3]), "r"(b[0]), "r"(b[1]));
}
__device__ __forceinline__ void split4h(float4 f, uint2& hi, uint2& lo) {
    __half a0 = __float2half_rn(f.x), a1 = __float2half_rn(f.y);
    __half a2 = __float2half_rn(f.z), a3 = __float2half_rn(f.w);
    __half b0 = __float2half_rn(f.x - __half2float(a0));
    __half b1 = __float2half_rn(f.y - __half2float(a1));
    __half b2 = __float2half_rn(f.z - __half2float(a2));
    __half b3 = __float2half_rn(f.w - __half2float(a3));
    __half2 h01(a0, a1), h23(a2, a3), l01(b0, b1), l23(b2, b3);
    hi = make_uint2(*(uint32_t*)&h01, *(uint32_t*)&h23);
    lo = make_uint2(*(uint32_t*)&l01, *(uint32_t*)&l23);
}
__device__ __forceinline__ uint2 cvt4h(float4 f) {
    __half2 h01 = __floats2half2_rn(f.x, f.y);
    __half2 h23 = __floats2half2_rn(f.z, f.w);
    return make_uint2(*(uint32_t*)&h01, *(uint32_t*)&h23);
}

// ===================== small kernels =====================
__global__ void zero_kernel() {
    int t = threadIdx.x;
    if (t < NE) g_cnt[t] = 0;
    if (t == NE) g_cnt[NE] = T_TOK;
}

__global__ void __launch_bounds__(256)
router_kernel(const float* __restrict__ x,
              const float* __restrict__ rw,
              const float* __restrict__ bias) {
    __shared__ float rwS[32][65];
    __shared__ float xS[8][64];
    int warp = threadIdx.x >> 5, lane = threadIdx.x & 31;
    int t = blockIdx.x * 8 + warp;

    float acc = 0.f;
    for (int h0 = 0; h0 < HID; h0 += 64) {
        __syncthreads();
        for (int i = threadIdx.x; i < 32 * 64; i += 256) {
            int e = i >> 6, j = i & 63;
            rwS[e][j] = rw[e * HID + h0 + j];
        }
        xS[warp][lane]      = x[(size_t)t * HID + h0 + lane];
        xS[warp][lane + 32] = x[(size_t)t * HID + h0 + 32 + lane];
        __syncthreads();
        #pragma unroll 8
        for (int j = 0; j < 64; j++)
            acc += xS[warp][j] * rwS[lane][j];
    }
    float score = 1.f / (1.f + __expf(-acc));
    float selv  = score + bias[lane];

    int   picks[TOPK];
    float pw[TOPK];
    float wsum = 0.f;
    #pragma unroll
    for (int k = 0; k < TOPK; k++) {
        float v = selv; int idx = lane;
        #pragma unroll
        for (int o = 16; o > 0; o >>= 1) {
            float v2 = __shfl_xor_sync(0xFFFFFFFFu, v, o);
            int   i2 = __shfl_xor_sync(0xFFFFFFFFu, idx, o);
            if (v2 > v || (v2 == v && i2 < idx)) { v = v2; idx = i2; }
        }
        picks[k] = idx;
        float w = __shfl_sync(0xFFFFFFFFu, score, idx);
        pw[k] = w; wsum += w;
        if (lane == idx) selv = -INFINITY;
    }
    if (lane == 0) {
        float inv = 1.f / (wsum + 1e-20f);
        #pragma unroll
        for (int k = 0; k < TOPK; k++) {
            int e = picks[k];
            int pos = atomicAdd(&g_cnt[e], 1);
            g_tok[e * T_TOK + pos] = t;
            g_w  [e * T_TOK + pos] = pw[k] * inv;
        }
        g_tok[NE * T_TOK + t] = t;
        g_w  [NE * T_TOK + t] = 1.0f;
    }
}

__global__ void build_tiles_kernel() {
    if (threadIdx.x == 0 && blockIdx.x == 0) {
        int off = 0, nt = 0;
        for (int e = 0; e < NE_TOT; e++) {
            g_off[e] = off;
            int c = g_cnt[e];
            for (int s = 0; s < c && nt < MAXTILES; s += BM) {
                g_tile_e[nt] = e; g_tile_s[nt] = s; nt++;
            }
            off += c;
        }
        g_off[NE_TOT] = off;
        g_ntiles = nt;
    }
}

// ===================== gate+up GEMM, fp16 2-pass, 3-stage ring =====================
// CTA: M128 x N64 (gate AND up). stage 24KB: A 16KB (128r x [32hi|32lo]);
// Bg 4KB | Bu 4KB. 3 buffers; stores of chunk c+1 interleave with MMA(c).
#define GU_SMEM (1024 + 3 * 24576)
__global__ void __launch_bounds__(256)
gu_gemm(const float* __restrict__ x,
        const float* __restrict__ wgR, const float* __restrict__ wuR,
        const float* __restrict__ wgS, const float* __restrict__ wuS) {
    extern __shared__ char sm[];
    uint32_t sa = smem_u32(sm);
    int* rowTokS = (int*)sm;

    int tilei = blockIdx.y;
    if (tilei >= g_ntiles) return;
    int e = g_tile_e[tilei], s0 = g_tile_s[tilei];
    int rows = min(BM, g_cnt[e] - s0);
    int hidbase = g_off[e] + s0;
    int N0 = blockIdx.x * 64;

    int tid = threadIdx.x, lane = tid & 31, wid = tid >> 5;
    int wm = wid & 3, wn = wid >> 2;

    if (tid < 128)
        rowTokS[tid] = g_tok[e * T_TOK + s0 + min(tid, rows - 1)];
    __syncthreads();

    const float* gptr = (e < NE) ? wgR + (size_t)e * HID * INTD : wgS;
    const float* uptr = (e < NE) ? wuR + (size_t)e * HID * INTD : wuS;

    int aRow = tid >> 3, aC4 = (tid & 7) * 4;
    int bK = tid >> 3,  bN4 = (tid & 7) * 4;
    int tokR[4];
    #pragma unroll
    for (int i = 0; i < 4; i++) tokR[i] = rowTokS[aRow + 32 * i];

    float4 fa[4], fg[2], fu[2];
    #pragma unroll
    for (int i = 0; i < 4; i++)
        fa[i] = *(const float4*)&x[(size_t)tokR[i] * HID + aC4];
    #pragma unroll
    for (int i = 0; i < 2; i++) {
        fg[i] = *(const float4*)&gptr[(size_t)bK * INTD + N0 + bN4 + 32 * i];
        fu[i] = *(const float4*)&uptr[(size_t)bK * INTD + N0 + bN4 + 32 * i];
    }

    float accG[2][4][4], accU[2][4][4];
    #pragma unroll
    for (int a = 0; a < 2; a++)
        #pragma unroll
        for (int b = 0; b < 4; b++)
            #pragma unroll
            for (int f = 0; f < 4; f++) { accG[a][b][f] = 0.f; accU[a][b][f] = 0.f; }

    const int KCH = HID / 32;
    int lm = lane & 15, lkh = lane >> 4;
    int swA = (aC4 * 2), swAx = ((aRow & 7) << 4);
    int swb = (bK & 7) << 4;

    // prologue: store chunk 0 -> buf0; prefetch chunk 1 into regs
    {
        char* nb = sm + 1024;
        #pragma unroll
        for (int i = 0; i < 4; i++) {
            int r = aRow + 32 * i; int sw = (r & 7) << 4;
            uint2 hi, lo; split4h(fa[i], hi, lo);
            *(uint2*)(nb + r * 128 + ((aC4 * 2)      ^ sw)) = hi;
            *(uint2*)(nb + r * 128 + ((aC4 * 2 + 64) ^ sw)) = lo;
        }
        char* nbB = nb + 16384;
        #pragma unroll
        for (int i = 0; i < 2; i++) {
            int nbo = (bN4 + 32 * i) * 2;
            *(uint2*)(nbB +        bK * 128 + (nbo ^ swb)) = cvt4h(fg[i]);
            *(uint2*)(nbB + 4096 + bK * 128 + (nbo ^ swb)) = cvt4h(fu[i]);
        }
        #pragma unroll
        for (int i = 0; i < 4; i++)
            fa[i] = *(const float4*)&x[(size_t)tokR[i] * HID + 32 + aC4];
        #pragma unroll
        for (int i = 0; i < 2; i++) {
            fg[i] = *(const float4*)&gptr[(size_t)(32 + bK) * INTD + N0 + bN4 + 32 * i];
            fu[i] = *(const float4*)&uptr[(size_t)(32 + bK) * INTD + N0 + bN4 + 32 * i];
        }
    }

    for (int c = 0; c < KCH; c++) {
        uint32_t As = sa + 1024 + (c % 3) * 24576;
        uint32_t Bg = As + 16384;
        char* nb = sm + 1024 + ((c + 1) % 3) * 24576;
        __syncthreads();

        // ---- MMA ks = 0 ----
        {
            const int ks = 0;
            uint32_t Gh[2][4], Uh[2][4];
            #pragma unroll
            for (int pr = 0; pr < 2; pr++) {
                int k = ks * 16 + lm;
                int n = wn * 32 + pr * 16 + lkh * 8;
                uint32_t ad = Bg + k * 128 + ((n * 2) ^ ((k & 7) << 4));
                ldsm_x4_t(Gh[pr], ad);
                ldsm_x4_t(Uh[pr], ad + 4096);
            }
            #pragma unroll
            for (int mt = 0; mt < 2; mt++) {
                int m = wm * 32 + mt * 16 + lm;
                int boff = (lkh * 16 + ks * 32) ^ ((m & 7) << 4);
                uint32_t Ah[4], Al[4];
                ldsm_x4(Ah, As + m * 128 + boff);
                ldsm_x4(Al, As + m * 128 + (boff ^ 64));
                #pragma unroll
                for (int nt = 0; nt < 4; nt++) {
                    mma_f16(accG[mt][nt], Ah, &Gh[nt >> 1][(nt & 1) * 2]);
                    mma_f16(accU[mt][nt], Ah, &Uh[nt >> 1][(nt & 1) * 2]);
                }
                #pragma unroll
                for (int nt = 0; nt < 4; nt++) {
                    mma_f16(accG[mt][nt], Al, &Gh[nt >> 1][(nt & 1) * 2]);
                    mma_f16(accU[mt][nt], Al, &Uh[nt >> 1][(nt & 1) * 2]);
                }
            }
        }

        // ---- store chunk c+1 (regs) -> ring buf; overlaps with MMA issue ----
        if (c + 1 < KCH) {
            #pragma unroll
            for (int i = 0; i < 4; i++) {
                int r = aRow + 32 * i; int sw = (r & 7) << 4;
                uint2 hi, lo; split4h(fa[i], hi, lo);
                *(uint2*)(nb + r * 128 + ((aC4 * 2)      ^ sw)) = hi;
                *(uint2*)(nb + r * 128 + ((aC4 * 2 + 64) ^ sw)) = lo;
            }
            char* nbB = nb + 16384;
            #pragma unroll
            for (int i = 0; i < 2; i++) {
                int nbo = (bN4 + 32 * i) * 2;
                *(uint2*)(nbB +        bK * 128 + (nbo ^ swb)) = cvt4h(fg[i]);
                *(uint2*)(nbB + 4096 + bK * 128 + (nbo ^ swb)) = cvt4h(fu[i]);
            }
        }
        // ---- prefetch chunk c+2 ----
        if (c + 2 < KCH) {
            int k0 = (c + 2) * 32;
            #pragma unroll
            for (int i = 0; i < 4; i++)
                fa[i] = *(const float4*)&x[(size_t)tokR[i] * HID + k0 + aC4];
            #pragma unroll
            for (int i = 0; i < 2; i++) {
                fg[i] = *(const float4*)&gptr[(size_t)(k0 + bK) * INTD + N0 + bN4 + 32 * i];
                fu[i] = *(const float4*)&uptr[(size_t)(k0 + bK) * INTD + N0 + bN4 + 32 * i];
            }
        }

        // ---- MMA ks = 1 ----
        {
            const int ks = 1;
            uint32_t Gh[2][4], Uh[2][4];
            #pragma unroll
            for (int pr = 0; pr < 2; pr++) {
                int k = ks * 16 + lm;
                int n = wn * 32 + pr * 16 + lkh * 8;
                uint32_t ad = Bg + k * 128 + ((n * 2) ^ ((k & 7) << 4));
                ldsm_x4_t(Gh[pr], ad);
                ldsm_x4_t(Uh[pr], ad + 4096);
            }
            #pragma unroll
            for (int mt = 0; mt < 2; mt++) {
                int m = wm * 32 + mt * 16 + lm;
                int boff = (lkh * 16 + ks * 32) ^ ((m & 7) << 4);
                uint32_t Ah[4], Al[4];
                ldsm_x4(Ah, As + m * 128 + boff);
                ldsm_x4(Al, As + m * 128 + (boff ^ 64));
                #pragma unroll
                for (int nt = 0; nt < 4; nt++) {
                    mma_f16(accG[mt][nt], Ah, &Gh[nt >> 1][(nt & 1) * 2]);
                    mma_f16(accU[mt][nt], Ah, &Uh[nt >> 1][(nt & 1) * 2]);
                }
                #pragma unroll
                for (int nt = 0; nt < 4; nt++) {
                    mma_f16(accG[mt][nt], Al, &Gh[nt >> 1][(nt & 1) * 2]);
                    mma_f16(accU[mt][nt], Al, &Uh[nt >> 1][(nt & 1) * 2]);
                }
            }
        }
    }

    // epilogue: fuse locally, write fp16 hi/lo planes
    int gr = lane >> 2, gc = (lane & 3) * 2;
    #pragma unroll
    for (int mt = 0; mt < 2; mt++) {
        #pragma unroll
        for (int nt = 0; nt < 4; nt++) {
            int col = N0 + wn * 32 + nt * 8 + gc;
            #pragma unroll
            for (int p = 0; p < 2; p++) {
                int r = wm * 32 + mt * 16 + gr + p * 8;
                if (r < rows) {
                    float g0 = accG[mt][nt][2 * p], g1 = accG[mt][nt][2 * p + 1];
                    float u0 = accU[mt][nt][2 * p], u1 = accU[mt][nt][2 * p + 1];
                    float h0 = (g0 / (1.f + __expf(-g0))) * u0;
                    float h1 = (g1 / (1.f + __expf(-g1))) * u1;
                    __half h0h = __float2half_rn(h0);
                    __half h1h = __float2half_rn(h1);
                    __half h0l = __float2half_rn(h0 - __half2float(h0h));
                    __half h1l = __float2half_rn(h1 - __half2float(h1h));
                    size_t o = (size_t)(hidbase + r) * INTD + col;
                    __half2 hh(h0h, h1h), ll(h0l, h1l);
                    *(uint32_t*)&g_hhi[o] = *(uint32_t*)&hh;
                    *(uint32_t*)&g_hlo[o] = *(uint32_t*)&ll;
                }
            }
        }
    }
}

// ===================== down GEMM, fp16 2-pass, 3-stage ring + scatter =====================
// CTA: M128 x N128. stage 24KB: A 16KB ; B 8KB (32k x 128n fp16, 256B rows).
#define DN_SMEM (1024 + 3 * 24576)
__global__ void __launch_bounds__(256)
dn_gemm(const float* __restrict__ wdR, const float* __restrict__ wdS,
        float* __restrict__ out) {
    extern __shared__ char sm[];
    uint32_t sa = smem_u32(sm);
    int* rowTokS = (int*)sm;
    float* rowWS = (float*)(sm + 512);

    int tilei = blockIdx.y;
    if (tilei >= g_ntiles) return;
    int e = g_tile_e[tilei], s0 = g_tile_s[tilei];
    int rows = min(BM, g_cnt[e] - s0);
    int hidbase = g_off[e] + s0;
    int N0 = blockIdx.x * 128;

    int tid = threadIdx.x, lane = tid & 31, wid = tid >> 5;
    int wm = wid & 3, wn = wid >> 2;

    if (tid < 128) {
        int idx = e * T_TOK + s0 + min(tid, rows - 1);
        rowTokS[tid] = g_tok[idx];
        rowWS[tid]   = g_w[idx];
    }
    __syncthreads();

    const float* wd = (e < NE) ? wdR + (size_t)e * INTD * HID : wdS;

    int aJ = tid & 3;
    int arR[2];
    #pragma unroll
    for (int i = 0; i < 2; i++)
        arR[i] = hidbase + min((tid >> 2) + 64 * i, rows - 1);
    int bK = tid >> 3, bN4 = (tid & 7) * 4;
    int swb = (bK & 7) << 4;

    uint4 ha[2], la[2];
    float4 fb[4];
    #pragma unroll
    for (int i = 0; i < 2; i++) {
        ha[i] = *(const uint4*)&g_hhi[(size_t)arR[i] * INTD + aJ * 8];
        la[i] = *(const uint4*)&g_hlo[(size_t)arR[i] * INTD + aJ * 8];
    }
    #pragma unroll
    for (int i = 0; i < 4; i++)
        fb[i] = *(const float4*)&wd[(size_t)bK * HID + N0 + bN4 + 32 * i];

    float acc[2][8][4];
    #pragma unroll
    for (int a = 0; a < 2; a++)
        #pragma unroll
        for (int b = 0; b < 8; b++)
            #pragma unroll
            for (int f = 0; f < 4; f++) acc[a][b][f] = 0.f;

    const int KCH = INTD / 32;
    int lm = lane & 15, lkh = lane >> 4;

    // prologue: store chunk 0 -> buf0; prefetch chunk 1
    {
        char* nb = sm + 1024;
        #pragma unroll
        for (int i = 0; i < 2; i++) {
            int r = (tid >> 2) + 64 * i; int sw = (r & 7) << 4;
            *(uint4*)(nb + r * 128 + ((aJ * 16)      ^ sw)) = ha[i];
            *(uint4*)(nb + r * 128 + ((aJ * 16 + 64) ^ sw)) = la[i];
        }
        char* nbB = nb + 16384;
        #pragma unroll
        for (int i = 0; i < 4; i++) {
            int nbo = (bN4 + 32 * i) * 2;
            *(uint2*)(nbB + bK * 256 + (nbo ^ swb)) = cvt4h(fb[i]);
        }
        #pragma unroll
        for (int i = 0; i < 2; i++) {
            ha[i] = *(const uint4*)&g_hhi[(size_t)arR[i] * INTD + 32 + aJ * 8];
            la[i] = *(const uint4*)&g_hlo[(size_t)arR[i] * INTD + 32 + aJ * 8];
        }
        #pragma unroll
        for (int i = 0; i < 4; i++)
            fb[i] = *(const float4*)&wd[(size_t)(32 + bK) * HID + N0 + bN4 + 32 * i];
    }

    for (int c = 0; c < KCH; c++) {
        uint32_t As = sa + 1024 + (c % 3) * 24576;
        uint32_t Bs = As + 16384;
        char* nb = sm + 1024 + ((c + 1) % 3) * 24576;
        __syncthreads();

        // ---- MMA ks = 0 ----
        {
            const int ks = 0;
            uint32_t Bh[4][4];
            #pragma unroll
            for (int h = 0; h < 2; h++)
                #pragma unroll
                for (int pr = 0; pr < 2; pr++) {
                    int k = ks * 16 + lm;
                    int n = wn * 64 + h * 32 + pr * 16 + lkh * 8;
                    uint32_t ad = Bs + k * 256 + ((n * 2) ^ ((k & 7) << 4));
                    ldsm_x4_t(Bh[h * 2 + pr], ad);
                }
            #pragma unroll
            for (int mt = 0; mt < 2; mt++) {
                int m = wm * 32 + mt * 16 + lm;
                int boff = (lkh * 16 + ks * 32) ^ ((m & 7) << 4);
                uint32_t Ah[4], Al[4];
                ldsm_x4(Ah, As + m * 128 + boff);
                ldsm_x4(Al, As + m * 128 + (boff ^ 64));
                #pragma unroll
                for (int nt = 0; nt < 8; nt++)
                    mma_f16(acc[mt][nt], Ah, &Bh[nt >> 1][(nt & 1) * 2]);
                #pragma unroll
                for (int nt = 0; nt < 8; nt++)
                    mma_f16(acc[mt][nt], Al, &Bh[nt >> 1][(nt & 1) * 2]);
            }
        }

        // ---- store chunk c+1 ----
        if (c + 1 < KCH) {
            #pragma unroll
            for (int i = 0; i < 2; i++) {
                int r = (tid >> 2) + 64 * i; int sw = (r & 7) << 4;
                *(uint4*)(nb + r * 128 + ((aJ * 16)      ^ sw)) = ha[i];
                *(uint4*)(nb + r * 128 + ((aJ * 16 + 64) ^ sw)) = la[i];
            }
            char* nbB = nb + 16384;
            #pragma unroll
            for (int i = 0; i < 4; i++) {
                int nbo = (bN4 + 32 * i) * 2;
                *(uint2*)(nbB + bK * 256 + (nbo ^ swb)) = cvt4h(fb[i]);
            }
        }
        // ---- prefetch chunk c+2 ----
        if (c + 2 < KCH) {
            int k0 = (c + 2) * 32;
            #pragma unroll
            for (int i = 0; i < 2; i++) {
                ha[i] = *(const uint4*)&g_hhi[(size_t)arR[i] * INTD + k0 + aJ * 8];
                la[i] = *(const uint4*)&g_hlo[(size_t)arR[i] * INTD + k0 + aJ * 8];
            }
            #pragma unroll
            for (int i = 0; i < 4; i++)
                fb[i] = *(const float4*)&wd[(size_t)(k0 + bK) * HID + N0 + bN4 + 32 * i];
        }

        // ---- MMA ks = 1 ----
        {
            const int ks = 1;
            uint32_t Bh[4][4];
            #pragma unroll
            for (int h = 0; h < 2; h++)
                #pragma unroll
                for (int pr = 0; pr < 2; pr++) {
                    int k = ks * 16 + lm;
                    int n = wn * 64 + h * 32 + pr * 16 + lkh * 8;
                    uint32_t ad = Bs + k * 256 + ((n * 2) ^ ((k & 7) << 4));
                    ldsm_x4_t(Bh[h * 2 + pr], ad);
                }
            #pragma unroll
            for (int mt = 0; mt < 2; mt++) {
                int m = wm * 32 + mt * 16 + lm;
                int boff = (lkh * 16 + ks * 32) ^ ((m & 7) << 4);
                uint32_t Ah[4], Al[4];
                ldsm_x4(Ah, As + m * 128 + boff);
                ldsm_x4(Al, As + m * 128 + (boff ^ 64));
                #pragma unroll
                for (int nt = 0; nt < 8; nt++)
                    mma_f16(acc[mt][nt], Ah, &Bh[nt >> 1][(nt & 1) * 2]);
                #pragma unroll
                for (int nt = 0; nt < 8; nt++)
                    mma_f16(acc[mt][nt], Al, &Bh[nt >> 1][(nt & 1) * 2]);
            }
        }
    }

    int gr = lane >> 2, gc = (lane & 3) * 2;
    #pragma unroll
    for (int mt = 0; mt < 2; mt++) {
        #pragma unroll
        for (int nt = 0; nt < 8; nt++) {
            int r0 = wm * 32 + mt * 16 + gr;
            int col = N0 + wn * 64 + nt * 8 + gc;
            if (r0 < rows) {
                int tok = rowTokS[r0]; float w = rowWS[r0];
                atomicAdd(&out[(size_t)tok * HID + col],     acc[mt][nt][0] * w);
                atomicAdd(&out[(size_t)tok * HID + col + 1], acc[mt][nt][1] * w);
            }
            if (r0 + 8 < rows) {
                int tok = rowTokS[r0 + 8]; float w = rowWS[r0 + 8];
                atomicAdd(&out[(size_t)tok * HID + col],     acc[mt][nt][2] * w);
                atomicAdd(&out[(size_t)tok * HID + col + 1], acc[mt][nt][3] * w);
            }
        }
    }
}

// ===================== launch =====================
extern "C" void kernel_launch(void* const* d_in, const int* in_sizes, int n_in,
                              void* d_out, int out_size) {
    const float* x    = (const float*)d_in[0];
    const float* rw   = (const float*)d_in[1];
    const float* bias = (const float*)d_in[2];
    const float* wg   = (const float*)d_in[3];
    const float* wu   = (const float*)d_in[4];
    const float* wd   = (const float*)d_in[5];
    const float* swg  = (const float*)d_in[6];
    const float* swu  = (const float*)d_in[7];
    const float* swd  = (const float*)d_in[8];
    float* out = (float*)d_out;

    cudaFuncSetAttribute(gu_gemm, cudaFuncAttributeMaxDynamicSharedMemorySize, GU_SMEM);
    cudaFuncSetAttribute(dn_gemm, cudaFuncAttributeMaxDynamicSharedMemorySize, DN_SMEM);

    cudaMemsetAsync(d_out, 0, (size_t)out_size * sizeof(float));
    zero_kernel<<<1, 64>>>();
    router_kernel<<<T_TOK / 8, 256>>>(x, rw, bias);
    build_tiles_kernel<<<1, 32>>>();

    gu_gemm<<<dim3(INTD / 64, MAXTILES), 256, GU_SMEM>>>(x, wg, wu, swg, swu);
    dn_gemm<<<dim3(HID / 128, MAXTILES), 256, DN_SMEM>>>(wd, swd, out);
}

// round 10
// speedup vs baseline: 1.0476x; 1.0476x over previous
#include <cuda_runtime.h>
#include <cuda_fp16.h>
#include <math.h>
#include <stdint.h>

#define T_TOK 2048
#define HID   2048
#define INTD  1024
#define NE    32
#define NE_TOT 33
#define TOPK  4
#define MAXTILES 128
#define BM    128
#define ROWS_MAX 10368

// ===================== device scratch =====================
__device__ int   g_cnt[NE_TOT];
__device__ int   g_tok[NE_TOT * T_TOK];
__device__ float g_w  [NE_TOT * T_TOK];
__device__ int   g_off[NE_TOT + 1];
__device__ int   g_tile_e[MAXTILES];
__device__ int   g_tile_s[MAXTILES];
__device__ int   g_ntiles;
// x split into fp16 hi/lo planes (precomputed once)
__device__ __align__(16) __half g_xhi[(size_t)T_TOK * HID];
__device__ __align__(16) __half g_xlo[(size_t)T_TOK * HID];
// intermediate h = silu(g)*u, single fp16 plane
__device__ __align__(16) __half g_hhi[(size_t)ROWS_MAX * INTD];

// ===================== PTX helpers =====================
__device__ __forceinline__ uint32_t smem_u32(const void* p) {
    uint32_t a;
    asm("{ .reg .u64 t; cvta.to.shared.u64 t, %1; cvt.u32.u64 %0, t; }" : "=r"(a) : "l"(p));
    return a;
}
__device__ __forceinline__ void ldsm_x4(uint32_t* r, uint32_t a) {
    asm volatile("ldmatrix.sync.aligned.m8n8.x4.shared.b16 {%0,%1,%2,%3}, [%4];"
                 : "=r"(r[0]), "=r"(r[1]), "=r"(r[2]), "=r"(r[3]) : "r"(a));
}
__device__ __forceinline__ void ldsm_x4_t(uint32_t* r, uint32_t a) {
    asm volatile("ldmatrix.sync.aligned.m8n8.x4.trans.shared.b16 {%0,%1,%2,%3}, [%4];"
                 : "=r"(r[0]), "=r"(r[1]), "=r"(r[2]), "=r"(r[3]) : "r"(a));
}
__device__ __forceinline__ void mma_f16(float* c, const uint32_t* a, const uint32_t* b) {
    asm volatile("mma.sync.aligned.m16n8k16.row.col.f32.f16.f16.f32 "
        "{%0,%1,%2,%3}, {%4,%5,%6,%7}, {%8,%9}, {%0,%1,%2,%3};"
        : "+f"(c[0]), "+f"(c[1]), "+f"(c[2]), "+f"(c[3])
        : "r"(a[0]), "r"(a[1]), "r"(a[2]), "r"(a[3]), "r"(b[0]), "r"(b[1]));
}
__device__ __forceinline__ void split4h(float4 f, uint2& hi, uint2& lo) {
    __half a0 = __float2half_rn(f.x), a1 = __float2half_rn(f.y);
    __half a2 = __float2half_rn(f.z), a3 = __float2half_rn(f.w);
    __half b0 = __float2half_rn(f.x - __half2float(a0));
    __half b1 = __float2half_rn(f.y - __half2float(a1));
    __half b2 = __float2half_rn(f.z - __half2float(a2));
    __half b3 = __float2half_rn(f.w - __half2float(a3));
    __half2 h01(a0, a1), h23(a2, a3), l01(b0, b1), l23(b2, b3);
    hi = make_uint2(*(uint32_t*)&h01, *(uint32_t*)&h23);
    lo = make_uint2(*(uint32_t*)&l01, *(uint32_t*)&l23);
}
__device__ __forceinline__ uint2 cvt4h(float4 f) {
    __half2 h01 = __floats2half2_rn(f.x, f.y);
    __half2 h23 = __floats2half2_rn(f.z, f.w);
    return make_uint2(*(uint32_t*)&h01, *(uint32_t*)&h23);
}

// ===================== small kernels =====================
__global__ void zero_kernel() {
    int t = threadIdx.x;
    if (t < NE) g_cnt[t] = 0;
    if (t == NE) g_cnt[NE] = T_TOK;
}

// x -> fp16 hi/lo planes
__global__ void __launch_bounds__(256)
prep_x(const float* __restrict__ x) {
    int n4 = T_TOK * HID / 4;
    for (int i = blockIdx.x * blockDim.x + threadIdx.x; i < n4;
         i += gridDim.x * blockDim.x) {
        float4 v = ((const float4*)x)[i];
        uint2 hi, lo; split4h(v, hi, lo);
        ((uint2*)g_xhi)[i] = hi;
        ((uint2*)g_xlo)[i] = lo;
    }
}

__global__ void __launch_bounds__(256)
router_kernel(const float* __restrict__ x,
              const float* __restrict__ rw,
              const float* __restrict__ bias) {
    __shared__ float rwS[32][65];
    __shared__ float xS[8][64];
    int warp = threadIdx.x >> 5, lane = threadIdx.x & 31;
    int t = blockIdx.x * 8 + warp;

    float acc = 0.f;
    for (int h0 = 0; h0 < HID; h0 += 64) {
        __syncthreads();
        for (int i = threadIdx.x; i < 32 * 64; i += 256) {
            int e = i >> 6, j = i & 63;
            rwS[e][j] = rw[e * HID + h0 + j];
        }
        xS[warp][lane]      = x[(size_t)t * HID + h0 + lane];
        xS[warp][lane + 32] = x[(size_t)t * HID + h0 + 32 + lane];
        __syncthreads();
        #pragma unroll 8
        for (int j = 0; j < 64; j++)
            acc += xS[warp][j] * rwS[lane][j];
    }
    float score = 1.f / (1.f + __expf(-acc));
    float selv  = score + bias[lane];

    int   picks[TOPK];
    float pw[TOPK];
    float wsum = 0.f;
    #pragma unroll
    for (int k = 0; k < TOPK; k++) {
        float v = selv; int idx = lane;
        #pragma unroll
        for (int o = 16; o > 0; o >>= 1) {
            float v2 = __shfl_xor_sync(0xFFFFFFFFu, v, o);
            int   i2 = __shfl_xor_sync(0xFFFFFFFFu, idx, o);
            if (v2 > v || (v2 == v && i2 < idx)) { v = v2; idx = i2; }
        }
        picks[k] = idx;
        float w = __shfl_sync(0xFFFFFFFFu, score, idx);
        pw[k] = w; wsum += w;
        if (lane == idx) selv = -INFINITY;
    }
    if (lane == 0) {
        float inv = 1.f / (wsum + 1e-20f);
        #pragma unroll
        for (int k = 0; k < TOPK; k++) {
            int e = picks[k];
            int pos = atomicAdd(&g_cnt[e], 1);
            g_tok[e * T_TOK + pos] = t;
            g_w  [e * T_TOK + pos] = pw[k] * inv;
        }
        g_tok[NE * T_TOK + t] = t;
        g_w  [NE * T_TOK + t] = 1.0f;
    }
}

__global__ void build_tiles_kernel() {
    if (threadIdx.x == 0 && blockIdx.x == 0) {
        int off = 0, nt = 0;
        for (int e = 0; e < NE_TOT; e++) {
            g_off[e] = off;
            int c = g_cnt[e];
            for (int s = 0; s < c && nt < MAXTILES; s += BM) {
                g_tile_e[nt] = e; g_tile_s[nt] = s; nt++;
            }
            off += c;
        }
        g_off[NE_TOT] = off;
        g_ntiles = nt;
    }
}

// ===================== gate+up GEMM, fp16 2-pass (A planes), fused SiLU =====================
// CTA: M128 x N64 (gate AND up). A from precomputed fp16 planes (raw uint4 loads).
// stage 24KB: A 16KB (128r x [32hi|32lo] halves) ; Bg 4KB | Bu 4KB.
// R8 pipeline: store(c) -> sync -> prefetch(c+1) -> MMA(c), 2 buffers.
#define GU_SMEM (1024 + 2 * 24576)
__global__ void __launch_bounds__(256)
gu_gemm(const float* __restrict__ wgR, const float* __restrict__ wuR,
        const float* __restrict__ wgS, const float* __restrict__ wuS) {
    extern __shared__ char sm[];
    uint32_t sa = smem_u32(sm);
    int* rowTokS = (int*)sm;

    int tilei = blockIdx.y;
    if (tilei >= g_ntiles) return;
    int e = g_tile_e[tilei], s0 = g_tile_s[tilei];
    int rows = min(BM, g_cnt[e] - s0);
    int hidbase = g_off[e] + s0;
    int N0 = blockIdx.x * 64;

    int tid = threadIdx.x, lane = tid & 31, wid = tid >> 5;
    int wm = wid & 3, wn = wid >> 2;

    if (tid < 128)
        rowTokS[tid] = g_tok[e * T_TOK + s0 + min(tid, rows - 1)];
    __syncthreads();

    const float* gptr = (e < NE) ? wgR + (size_t)e * HID * INTD : wgS;
    const float* uptr = (e < NE) ? wuR + (size_t)e * HID * INTD : wuS;

    int aJ = tid & 3;                 // 16B k-granule (8 halves)
    int bK = tid >> 3, bN4 = (tid & 7) * 4;
    int tokR[2];
    #pragma unroll
    for (int i = 0; i < 2; i++) tokR[i] = rowTokS[(tid >> 2) + 64 * i];

    uint4 ha[2], la[2];
    float4 fg[2], fu[2];
    #pragma unroll
    for (int i = 0; i < 2; i++) {
        ha[i] = *(const uint4*)&g_xhi[(size_t)tokR[i] * HID + aJ * 8];
        la[i] = *(const uint4*)&g_xlo[(size_t)tokR[i] * HID + aJ * 8];
    }
    #pragma unroll
    for (int i = 0; i < 2; i++) {
        fg[i] = *(const float4*)&gptr[(size_t)bK * INTD + N0 + bN4 + 32 * i];
        fu[i] = *(const float4*)&uptr[(size_t)bK * INTD + N0 + bN4 + 32 * i];
    }

    float accG[2][4][4], accU[2][4][4];
    #pragma unroll
    for (int a = 0; a < 2; a++)
        #pragma unroll
        for (int b = 0; b < 4; b++)
            #pragma unroll
            for (int f = 0; f < 4; f++) { accG[a][b][f] = 0.f; accU[a][b][f] = 0.f; }

    const int KCH = HID / 32;
    int lm = lane & 15, lkh = lane >> 4;
    int swb = (bK & 7) << 4;

    for (int c = 0; c < KCH; c++) {
        char* base = sm + 1024 + (c & 1) * 24576;
        uint32_t As = sa + 1024 + (c & 1) * 24576;
        uint32_t Bg = As + 16384;
        char* Asm = base;
        char* Bsm = base + 16384;

        #pragma unroll
        for (int i = 0; i < 2; i++) {
            int r = (tid >> 2) + 64 * i; int sw = (r & 7) << 4;
            *(uint4*)(Asm + r * 128 + ((aJ * 16)      ^ sw)) = ha[i];
            *(uint4*)(Asm + r * 128 + ((aJ * 16 + 64) ^ sw)) = la[i];
        }
        #pragma unroll
        for (int i = 0; i < 2; i++) {
            int nb = (bN4 + 32 * i) * 2;
            *(uint2*)(Bsm +        bK * 128 + (nb ^ swb)) = cvt4h(fg[i]);
            *(uint2*)(Bsm + 4096 + bK * 128 + (nb ^ swb)) = cvt4h(fu[i]);
        }
        __syncthreads();

        if (c + 1 < KCH) {
            int k0 = (c + 1) * 32;
            #pragma unroll
            for (int i = 0; i < 2; i++) {
                ha[i] = *(const uint4*)&g_xhi[(size_t)tokR[i] * HID + k0 + aJ * 8];
                la[i] = *(const uint4*)&g_xlo[(size_t)tokR[i] * HID + k0 + aJ * 8];
            }
            #pragma unroll
            for (int i = 0; i < 2; i++) {
                fg[i] = *(const float4*)&gptr[(size_t)(k0 + bK) * INTD + N0 + bN4 + 32 * i];
                fu[i] = *(const float4*)&uptr[(size_t)(k0 + bK) * INTD + N0 + bN4 + 32 * i];
            }
        }

        #pragma unroll
        for (int ks = 0; ks < 2; ks++) {
            uint32_t Gh[2][4], Uh[2][4];
            #pragma unroll
            for (int pr = 0; pr < 2; pr++) {
                int k = ks * 16 + lm;
                int n = wn * 32 + pr * 16 + lkh * 8;
                uint32_t ad = Bg + k * 128 + ((n * 2) ^ ((k & 7) << 4));
                ldsm_x4_t(Gh[pr], ad);
                ldsm_x4_t(Uh[pr], ad + 4096);
            }
            #pragma unroll
            for (int mt = 0; mt < 2; mt++) {
                int m = wm * 32 + mt * 16 + lm;
                int boff = (lkh * 16 + ks * 32) ^ ((m & 7) << 4);
                uint32_t Ah[4], Al[4];
                ldsm_x4(Ah, As + m * 128 + boff);
                ldsm_x4(Al, As + m * 128 + (boff ^ 64));
                #pragma unroll
                for (int nt = 0; nt < 4; nt++) {
                    mma_f16(accG[mt][nt], Ah, &Gh[nt >> 1][(nt & 1) * 2]);
                    mma_f16(accU[mt][nt], Ah, &Uh[nt >> 1][(nt & 1) * 2]);
                }
                #pragma unroll
                for (int nt = 0; nt < 4; nt++) {
                    mma_f16(accG[mt][nt], Al, &Gh[nt >> 1][(nt & 1) * 2]);
                    mma_f16(accU[mt][nt], Al, &Uh[nt >> 1][(nt & 1) * 2]);
                }
            }
        }
        __syncthreads();
    }

    // epilogue: fuse locally, write single fp16 plane
    int gr = lane >> 2, gc = (lane & 3) * 2;
    #pragma unroll
    for (int mt = 0; mt < 2; mt++) {
        #pragma unroll
        for (int nt = 0; nt < 4; nt++) {
            int col = N0 + wn * 32 + nt * 8 + gc;
            #pragma unroll
            for (int p = 0; p < 2; p++) {
                int r = wm * 32 + mt * 16 + gr + p * 8;
                if (r < rows) {
                    float g0 = accG[mt][nt][2 * p], g1 = accG[mt][nt][2 * p + 1];
                    float u0 = accU[mt][nt][2 * p], u1 = accU[mt][nt][2 * p + 1];
                    float h0 = (g0 / (1.f + __expf(-g0))) * u0;
                    float h1 = (g1 / (1.f + __expf(-g1))) * u1;
                    __half2 hh(__float2half_rn(h0), __float2half_rn(h1));
                    size_t o = (size_t)(hidbase + r) * INTD + col;
                    *(uint32_t*)&g_hhi[o] = *(uint32_t*)&hh;
                }
            }
        }
    }
}

// ===================== down GEMM, fp16 SINGLE-pass A + weighted scatter =====================
// CTA: M128 x N128. A = h single fp16 plane, chunk k=64 (A rows 128B = SW128).
// stage 32KB: A 16KB (128r x 64 halves) ; B 16KB (64k x 128n fp16, 256B rows).
// MMA: 1 pass (Ah only) -> half the MMA work of R8's dn.
#define DN_SMEM (1024 + 2 * 32768)
__global__ void __launch_bounds__(256)
dn_gemm(const float* __restrict__ wdR, const float* __restrict__ wdS,
        float* __restrict__ out) {
    extern __shared__ char sm[];
    uint32_t sa = smem_u32(sm);
    int* rowTokS = (int*)sm;
    float* rowWS = (float*)(sm + 512);

    int tilei = blockIdx.y;
    if (tilei >= g_ntiles) return;
    int e = g_tile_e[tilei], s0 = g_tile_s[tilei];
    int rows = min(BM, g_cnt[e] - s0);
    int hidbase = g_off[e] + s0;
    int N0 = blockIdx.x * 128;

    int tid = threadIdx.x, lane = tid & 31, wid = tid >> 5;
    int wm = wid & 3, wn = wid >> 2;

    if (tid < 128) {
        int idx = e * T_TOK + s0 + min(tid, rows - 1);
        rowTokS[tid] = g_tok[idx];
        rowWS[tid]   = g_w[idx];
    }
    __syncthreads();

    const float* wd = (e < NE) ? wdR + (size_t)e * INTD * HID : wdS;

    // A: granule aJ = tid&7 (8 of them = 64 halves), rows (tid>>3)+32i, i<4
    int aJ = tid & 7;
    int arR[4];
    #pragma unroll
    for (int i = 0; i < 4; i++)
        arR[i] = hidbase + min((tid >> 3) + 32 * i, rows - 1);
    // B: 64 rows x 128 cols fp16; per thread 8 float4: row bK=tid>>2, cols (tid&3)*4 + 16j
    int bK = tid >> 2, bC = (tid & 3) * 4;

    uint4 ha[4];
    float4 fb[8];
    #pragma unroll
    for (int i = 0; i < 4; i++)
        ha[i] = *(const uint4*)&g_hhi[(size_t)arR[i] * INTD + aJ * 8];
    #pragma unroll
    for (int j = 0; j < 8; j++)
        fb[j] = *(const float4*)&wd[(size_t)bK * HID + N0 + bC + 16 * j];

    float acc[2][8][4];
    #pragma unroll
    for (int a = 0; a < 2; a++)
        #pragma unroll
        for (int b = 0; b < 8; b++)
            #pragma unroll
            for (int f = 0; f < 4; f++) acc[a][b][f] = 0.f;

    const int KCH = INTD / 64;
    int lm = lane & 15, lkh = lane >> 4;
    int swb = (bK & 7) << 4;

    for (int c = 0; c < KCH; c++) {
        char* base = sm + 1024 + (c & 1) * 32768;
        uint32_t As = sa + 1024 + (c & 1) * 32768;
        uint32_t Bs = As + 16384;
        char* Asm = base;
        char* Bsm = base + 16384;

        #pragma unroll
        for (int i = 0; i < 4; i++) {
            int r = (tid >> 3) + 32 * i; int sw = (r & 7) << 4;
            *(uint4*)(Asm + r * 128 + ((aJ * 16) ^ sw)) = ha[i];
        }
        #pragma unroll
        for (int j = 0; j < 8; j++) {
            int nb = (bC + 16 * j) * 2;
            *(uint2*)(Bsm + bK * 256 + (nb ^ swb)) = cvt4h(fb[j]);
        }
        __syncthreads();

        if (c + 1 < KCH) {
            int k0 = (c + 1) * 64;
            #pragma unroll
            for (int i = 0; i < 4; i++)
                ha[i] = *(const uint4*)&g_hhi[(size_t)arR[i] * INTD + k0 + aJ * 8];
            #pragma unroll
            for (int j = 0; j < 8; j++)
                fb[j] = *(const float4*)&wd[(size_t)(k0 + bK) * HID + N0 + bC + 16 * j];
        }

        #pragma unroll
        for (int ks = 0; ks < 4; ks++) {
            uint32_t Bh[4][4];
            #pragma unroll
            for (int h = 0; h < 2; h++)
                #pragma unroll
                for (int pr = 0; pr < 2; pr++) {
                    int k = ks * 16 + lm;
                    int n = wn * 64 + h * 32 + pr * 16 + lkh * 8;
                    uint32_t ad = Bs + k * 256 + ((n * 2) ^ ((k & 7) << 4));
                    ldsm_x4_t(Bh[h * 2 + pr], ad);
                }
            #pragma unroll
            for (int mt = 0; mt < 2; mt++) {
                int m = wm * 32 + mt * 16 + lm;
                int boff = (lkh * 16 + ks * 32) ^ ((m & 7) << 4);
                uint32_t Ah[4];
                ldsm_x4(Ah, As + m * 128 + boff);
                #pragma unroll
                for (int nt = 0; nt < 8; nt++)
                    mma_f16(acc[mt][nt], Ah, &Bh[nt >> 1][(nt & 1) * 2]);
            }
        }
        __syncthreads();
    }

    int gr = lane >> 2, gc = (lane & 3) * 2;
    #pragma unroll
    for (int mt = 0; mt < 2; mt++) {
        #pragma unroll
        for (int nt = 0; nt < 8; nt++) {
            int r0 = wm * 32 + mt * 16 + gr;
            int col = N0 + wn * 64 + nt * 8 + gc;
            if (r0 < rows) {
                int tok = rowTokS[r0]; float w = rowWS[r0];
                atomicAdd(&out[(size_t)tok * HID + col],     acc[mt][nt][0] * w);
                atomicAdd(&out[(size_t)tok * HID + col + 1], acc[mt][nt][1] * w);
            }
            if (r0 + 8 < rows) {
                int tok = rowTokS[r0 + 8]; float w = rowWS[r0 + 8];
                atomicAdd(&out[(size_t)tok * HID + col],     acc[mt][nt][2] * w);
                atomicAdd(&out[(size_t)tok * HID + col + 1], acc[mt][nt][3] * w);
            }
        }
    }
}

// ===================== launch =====================
extern "C" void kernel_launch(void* const* d_in, const int* in_sizes, int n_in,
                              void* d_out, int out_size) {
    const float* x    = (const float*)d_in[0];
    const float* rw   = (const float*)d_in[1];
    const float* bias = (const float*)d_in[2];
    const float* wg   = (const float*)d_in[3];
    const float* wu   = (const float*)d_in[4];
    const float* wd   = (const float*)d_in[5];
    const float* swg  = (const float*)d_in[6];
    const float* swu  = (const float*)d_in[7];
    const float* swd  = (const float*)d_in[8];
    float* out = (float*)d_out;

    cudaFuncSetAttribute(gu_gemm, cudaFuncAttributeMaxDynamicSharedMemorySize, GU_SMEM);
    cudaFuncSetAttribute(dn_gemm, cudaFuncAttributeMaxDynamicSharedMemorySize, DN_SMEM);

    cudaMemsetAsync(d_out, 0, (size_t)out_size * sizeof(float));
    zero_kernel<<<1, 64>>>();
    prep_x<<<2048, 256>>>(x);
    router_kernel<<<T_TOK / 8, 256>>>(x, rw, bias);
    build_tiles_kernel<<<1, 32>>>();

    gu_gemm<<<dim3(INTD / 64, MAXTILES), 256, GU_SMEM>>>(wg, wu, swg, swu);
    dn_gemm<<<dim3(HID / 128, MAXTILES), 256, DN_SMEM>>>(wd, swd, out);
}

// round 12
// speedup vs baseline: 1.4180x; 1.3536x over previous
#include <cuda_runtime.h>
#include <cuda_fp16.h>
#include <math.h>
#include <stdint.h>

#define T_TOK 2048
#define HID   2048
#define INTD  1024
#define NE    32
#define NE_TOT 33
#define TOPK  4
#define MAXTILES 128
#define BM    128
#define ROWS_MAX 10368

// ===================== device scratch =====================
__device__ int   g_cnt[NE_TOT];
__device__ int   g_tok[NE_TOT * T_TOK];
__device__ float g_w  [NE_TOT * T_TOK];
__device__ int   g_off[NE_TOT + 1];
__device__ int   g_tile_e[MAXTILES];
__device__ int   g_tile_s[MAXTILES];
__device__ int   g_ntiles;
// x as single fp16 plane (precomputed once)
__device__ __align__(16) __half g_xhi[(size_t)T_TOK * HID];
// intermediate h = silu(g)*u, single fp16 plane
__device__ __align__(16) __half g_hhi[(size_t)ROWS_MAX * INTD];

// ===================== PTX helpers =====================
__device__ __forceinline__ uint32_t smem_u32(const void* p) {
    uint32_t a;
    asm("{ .reg .u64 t; cvta.to.shared.u64 t, %1; cvt.u32.u64 %0, t; }" : "=r"(a) : "l"(p));
    return a;
}
__device__ __forceinline__ void ldsm_x4(uint32_t* r, uint32_t a) {
    asm volatile("ldmatrix.sync.aligned.m8n8.x4.shared.b16 {%0,%1,%2,%3}, [%4];"
                 : "=r"(r[0]), "=r"(r[1]), "=r"(r[2]), "=r"(r[3]) : "r"(a));
}
__device__ __forceinline__ void ldsm_x4_t(uint32_t* r, uint32_t a) {
    asm volatile("ldmatrix.sync.aligned.m8n8.x4.trans.shared.b16 {%0,%1,%2,%3}, [%4];"
                 : "=r"(r[0]), "=r"(r[1]), "=r"(r[2]), "=r"(r[3]) : "r"(a));
}
__device__ __forceinline__ void mma_f16(float* c, const uint32_t* a, const uint32_t* b) {
    asm volatile("mma.sync.aligned.m16n8k16.row.col.f32.f16.f16.f32 "
        "{%0,%1,%2,%3}, {%4,%5,%6,%7}, {%8,%9}, {%0,%1,%2,%3};"
        : "+f"(c[0]), "+f"(c[1]), "+f"(c[2]), "+f"(c[3])
        : "r"(a[0]), "r"(a[1]), "r"(a[2]), "r"(a[3]), "r"(b[0]), "r"(b[1]));
}
__device__ __forceinline__ uint2 cvt4h(float4 f) {
    __half2 h01 = __floats2half2_rn(f.x, f.y);
    __half2 h23 = __floats2half2_rn(f.z, f.w);
    return make_uint2(*(uint32_t*)&h01, *(uint32_t*)&h23);
}

// ===================== small kernels =====================
__global__ void zero_kernel() {
    int t = threadIdx.x;
    if (t < NE) g_cnt[t] = 0;
    if (t == NE) g_cnt[NE] = T_TOK;
}

// x -> fp16 plane
__global__ void __launch_bounds__(256)
prep_x(const float* __restrict__ x) {
    int n4 = T_TOK * HID / 4;
    for (int i = blockIdx.x * blockDim.x + threadIdx.x; i < n4;
         i += gridDim.x * blockDim.x) {
        float4 v = ((const float4*)x)[i];
        ((uint2*)g_xhi)[i] = cvt4h(v);
    }
}

__global__ void __launch_bounds__(256)
router_kernel(const float* __restrict__ x,
              const float* __restrict__ rw,
              const float* __restrict__ bias) {
    __shared__ float rwS[32][65];
    __shared__ float xS[8][64];
    int warp = threadIdx.x >> 5, lane = threadIdx.x & 31;
    int t = blockIdx.x * 8 + warp;

    float acc = 0.f;
    for (int h0 = 0; h0 < HID; h0 += 64) {
        __syncthreads();
        for (int i = threadIdx.x; i < 32 * 64; i += 256) {
            int e = i >> 6, j = i & 63;
            rwS[e][j] = rw[e * HID + h0 + j];
        }
        xS[warp][lane]      = x[(size_t)t * HID + h0 + lane];
        xS[warp][lane + 32] = x[(size_t)t * HID + h0 + 32 + lane];
        __syncthreads();
        #pragma unroll 8
        for (int j = 0; j < 64; j++)
            acc += xS[warp][j] * rwS[lane][j];
    }
    float score = 1.f / (1.f + __expf(-acc));
    float selv  = score + bias[lane];

    int   picks[TOPK];
    float pw[TOPK];
    float wsum = 0.f;
    #pragma unroll
    for (int k = 0; k < TOPK; k++) {
        float v = selv; int idx = lane;
        #pragma unroll
        for (int o = 16; o > 0; o >>= 1) {
            float v2 = __shfl_xor_sync(0xFFFFFFFFu, v, o);
            int   i2 = __shfl_xor_sync(0xFFFFFFFFu, idx, o);
            if (v2 > v || (v2 == v && i2 < idx)) { v = v2; idx = i2; }
        }
        picks[k] = idx;
        float w = __shfl_sync(0xFFFFFFFFu, score, idx);
        pw[k] = w; wsum += w;
        if (lane == idx) selv = -INFINITY;
    }
    if (lane == 0) {
        float inv = 1.f / (wsum + 1e-20f);
        #pragma unroll
        for (int k = 0; k < TOPK; k++) {
            int e = picks[k];
            int pos = atomicAdd(&g_cnt[e], 1);
            g_tok[e * T_TOK + pos] = t;
            g_w  [e * T_TOK + pos] = pw[k] * inv;
        }
        g_tok[NE * T_TOK + t] = t;
        g_w  [NE * T_TOK + t] = 1.0f;
    }
}

__global__ void build_tiles_kernel() {
    if (threadIdx.x == 0 && blockIdx.x == 0) {
        int off = 0, nt = 0;
        for (int e = 0; e < NE_TOT; e++) {
            g_off[e] = off;
            int c = g_cnt[e];
            for (int s = 0; s < c && nt < MAXTILES; s += BM) {
                g_tile_e[nt] = e; g_tile_s[nt] = s; nt++;
            }
            off += c;
        }
        g_off[NE_TOT] = off;
        g_ntiles = nt;
    }
}

// ===================== gate+up GEMM, fp16 single-pass, fused SiLU =====================
// CTA: M128 x N64 (gate AND up). A = x fp16 plane (gathered), chunk k=64.
// stage 32KB: A 16KB (128r x 64 halves, SW128) ; Bg 8KB | Bu 8KB (64k x 64n).
// FIX (R11 NaN): B granule loop must be j<4 (4 float4 per matrix per thread)
// to cover all 64 columns; j<2 left half of Bg/Bu smem uninitialized.
#define GU_SMEM (1024 + 2 * 32768)
__global__ void __launch_bounds__(256)
gu_gemm(const float* __restrict__ wgR, const float* __restrict__ wuR,
        const float* __restrict__ wgS, const float* __restrict__ wuS) {
    extern __shared__ char sm[];
    uint32_t sa = smem_u32(sm);
    int* rowTokS = (int*)sm;

    int tilei = blockIdx.y;
    if (tilei >= g_ntiles) return;
    int e = g_tile_e[tilei], s0 = g_tile_s[tilei];
    int rows = min(BM, g_cnt[e] - s0);
    int hidbase = g_off[e] + s0;
    int N0 = blockIdx.x * 64;

    int tid = threadIdx.x, lane = tid & 31, wid = tid >> 5;
    int wm = wid & 3, wn = wid >> 2;

    if (tid < 128)
        rowTokS[tid] = g_tok[e * T_TOK + s0 + min(tid, rows - 1)];
    __syncthreads();

    const float* gptr = (e < NE) ? wgR + (size_t)e * HID * INTD : wgS;
    const float* uptr = (e < NE) ? wuR + (size_t)e * HID * INTD : wuS;

    // A: rows (tid>>3)+32i (i<4), granule aJ=tid&7 (16B = 8 halves)
    int aJ = tid & 7;
    int tokR[4];
    #pragma unroll
    for (int i = 0; i < 4; i++)
        tokR[i] = rowTokS[(tid >> 3) + 32 * i];
    // B: each matrix 64k x 64n fp32; per thread row bK=tid>>2, cols bC+16j (j<4)
    int bK = tid >> 2, bC = (tid & 3) * 4;

    uint4 ha[4];
    float4 fg[4], fu[4];
    #pragma unroll
    for (int i = 0; i < 4; i++)
        ha[i] = *(const uint4*)&g_xhi[(size_t)tokR[i] * HID + aJ * 8];
    #pragma unroll
    for (int j = 0; j < 4; j++) {
        fg[j] = *(const float4*)&gptr[(size_t)bK * INTD + N0 + bC + 16 * j];
        fu[j] = *(const float4*)&uptr[(size_t)bK * INTD + N0 + bC + 16 * j];
    }

    float accG[2][4][4], accU[2][4][4];
    #pragma unroll
    for (int a = 0; a < 2; a++)
        #pragma unroll
        for (int b = 0; b < 4; b++)
            #pragma unroll
            for (int f = 0; f < 4; f++) { accG[a][b][f] = 0.f; accU[a][b][f] = 0.f; }

    const int KCH = HID / 64;
    int lm = lane & 15, lkh = lane >> 4;
    int swb = (bK & 7) << 4;

    for (int c = 0; c < KCH; c++) {
        char* base = sm + 1024 + (c & 1) * 32768;
        uint32_t As = sa + 1024 + (c & 1) * 32768;
        uint32_t Bg = As + 16384;   // gate 8KB (64 rows x 128B); up at +8192
        char* Asm = base;
        char* Bsm = base + 16384;

        #pragma unroll
        for (int i = 0; i < 4; i++) {
            int r = (tid >> 3) + 32 * i; int sw = (r & 7) << 4;
            *(uint4*)(Asm + r * 128 + ((aJ * 16) ^ sw)) = ha[i];
        }
        #pragma unroll
        for (int j = 0; j < 4; j++) {
            int nb = (bC + 16 * j) * 2;
            *(uint2*)(Bsm +        bK * 128 + (nb ^ swb)) = cvt4h(fg[j]);
            *(uint2*)(Bsm + 8192 + bK * 128 + (nb ^ swb)) = cvt4h(fu[j]);
        }
        __syncthreads();

        if (c + 1 < KCH) {
            int k0 = (c + 1) * 64;
            #pragma unroll
            for (int i = 0; i < 4; i++)
                ha[i] = *(const uint4*)&g_xhi[(size_t)tokR[i] * HID + k0 + aJ * 8];
            #pragma unroll
            for (int j = 0; j < 4; j++) {
                fg[j] = *(const float4*)&gptr[(size_t)(k0 + bK) * INTD + N0 + bC + 16 * j];
                fu[j] = *(const float4*)&uptr[(size_t)(k0 + bK) * INTD + N0 + bC + 16 * j];
            }
        }

        #pragma unroll
        for (int ks = 0; ks < 4; ks++) {
            uint32_t Gh[2][4], Uh[2][4];
            #pragma unroll
            for (int pr = 0; pr < 2; pr++) {
                int k = ks * 16 + lm;
                int n = wn * 32 + pr * 16 + lkh * 8;
                uint32_t ad = Bg + k * 128 + ((n * 2) ^ ((k & 7) << 4));
                ldsm_x4_t(Gh[pr], ad);
                ldsm_x4_t(Uh[pr], ad + 8192);
            }
            #pragma unroll
            for (int mt = 0; mt < 2; mt++) {
                int m = wm * 32 + mt * 16 + lm;
                int boff = (lkh * 16 + ks * 32) ^ ((m & 7) << 4);
                uint32_t Ah[4];
                ldsm_x4(Ah, As + m * 128 + boff);
                #pragma unroll
                for (int nt = 0; nt < 4; nt++) {
                    mma_f16(accG[mt][nt], Ah, &Gh[nt >> 1][(nt & 1) * 2]);
                    mma_f16(accU[mt][nt], Ah, &Uh[nt >> 1][(nt & 1) * 2]);
                }
            }
        }
        __syncthreads();
    }

    // epilogue: fuse locally, write single fp16 plane
    int gr = lane >> 2, gc = (lane & 3) * 2;
    #pragma unroll
    for (int mt = 0; mt < 2; mt++) {
        #pragma unroll
        for (int nt = 0; nt < 4; nt++) {
            int col = N0 + wn * 32 + nt * 8 + gc;
            #pragma unroll
            for (int p = 0; p < 2; p++) {
                int r = wm * 32 + mt * 16 + gr + p * 8;
                if (r < rows) {
                    float g0 = accG[mt][nt][2 * p], g1 = accG[mt][nt][2 * p + 1];
                    float u0 = accU[mt][nt][2 * p], u1 = accU[mt][nt][2 * p + 1];
                    float h0 = (g0 / (1.f + __expf(-g0))) * u0;
                    float h1 = (g1 / (1.f + __expf(-g1))) * u1;
                    __half2 hh(__float2half_rn(h0), __float2half_rn(h1));
                    size_t o = (size_t)(hidbase + r) * INTD + col;
                    *(uint32_t*)&g_hhi[o] = *(uint32_t*)&hh;
                }
            }
        }
    }
}

// ===================== down GEMM, fp16 single-pass + weighted scatter =====================
// CTA: M128 x N128. A = h fp16 plane, chunk k=64.
// stage 32KB: A 16KB ; B 16KB (64k x 128n fp16, 256B rows).
#define DN_SMEM (1024 + 2 * 32768)
__global__ void __launch_bounds__(256)
dn_gemm(const float* __restrict__ wdR, const float* __restrict__ wdS,
        float* __restrict__ out) {
    extern __shared__ char sm[];
    uint32_t sa = smem_u32(sm);
    int* rowTokS = (int*)sm;
    float* rowWS = (float*)(sm + 512);

    int tilei = blockIdx.y;
    if (tilei >= g_ntiles) return;
    int e = g_tile_e[tilei], s0 = g_tile_s[tilei];
    int rows = min(BM, g_cnt[e] - s0);
    int hidbase = g_off[e] + s0;
    int N0 = blockIdx.x * 128;

    int tid = threadIdx.x, lane = tid & 31, wid = tid >> 5;
    int wm = wid & 3, wn = wid >> 2;

    if (tid < 128) {
        int idx = e * T_TOK + s0 + min(tid, rows - 1);
        rowTokS[tid] = g_tok[idx];
        rowWS[tid]   = g_w[idx];
    }
    __syncthreads();

    const float* wd = (e < NE) ? wdR + (size_t)e * INTD * HID : wdS;

    int aJ = tid & 7;
    int arR[4];
    #pragma unroll
    for (int i = 0; i < 4; i++)
        arR[i] = hidbase + min((tid >> 3) + 32 * i, rows - 1);
    int bK = tid >> 2, bC = (tid & 3) * 4;

    uint4 ha[4];
    float4 fb[8];
    #pragma unroll
    for (int i = 0; i < 4; i++)
        ha[i] = *(const uint4*)&g_hhi[(size_t)arR[i] * INTD + aJ * 8];
    #pragma unroll
    for (int j = 0; j < 8; j++)
        fb[j] = *(const float4*)&wd[(size_t)bK * HID + N0 + bC + 16 * j];

    float acc[2][8][4];
    #pragma unroll
    for (int a = 0; a < 2; a++)
        #pragma unroll
        for (int b = 0; b < 8; b++)
            #pragma unroll
            for (int f = 0; f < 4; f++) acc[a][b][f] = 0.f;

    const int KCH = INTD / 64;
    int lm = lane & 15, lkh = lane >> 4;
    int swb = (bK & 7) << 4;

    for (int c = 0; c < KCH; c++) {
        char* base = sm + 1024 + (c & 1) * 32768;
        uint32_t As = sa + 1024 + (c & 1) * 32768;
        uint32_t Bs = As + 16384;
        char* Asm = base;
        char* Bsm = base + 16384;

        #pragma unroll
        for (int i = 0; i < 4; i++) {
            int r = (tid >> 3) + 32 * i; int sw = (r & 7) << 4;
            *(uint4*)(Asm + r * 128 + ((aJ * 16) ^ sw)) = ha[i];
        }
        #pragma unroll
        for (int j = 0; j < 8; j++) {
            int nb = (bC + 16 * j) * 2;
            *(uint2*)(Bsm + bK * 256 + (nb ^ swb)) = cvt4h(fb[j]);
        }
        __syncthreads();

        if (c + 1 < KCH) {
            int k0 = (c + 1) * 64;
            #pragma unroll
            for (int i = 0; i < 4; i++)
                ha[i] = *(const uint4*)&g_hhi[(size_t)arR[i] * INTD + k0 + aJ * 8];
            #pragma unroll
            for (int j = 0; j < 8; j++)
                fb[j] = *(const float4*)&wd[(size_t)(k0 + bK) * HID + N0 + bC + 16 * j];
        }

        #pragma unroll
        for (int ks = 0; ks < 4; ks++) {
            uint32_t Bh[4][4];
            #pragma unroll
            for (int h = 0; h < 2; h++)
                #pragma unroll
                for (int pr = 0; pr < 2; pr++) {
                    int k = ks * 16 + lm;
                    int n = wn * 64 + h * 32 + pr * 16 + lkh * 8;
                    uint32_t ad = Bs + k * 256 + ((n * 2) ^ ((k & 7) << 4));
                    ldsm_x4_t(Bh[h * 2 + pr], ad);
                }
            #pragma unroll
            for (int mt = 0; mt < 2; mt++) {
                int m = wm * 32 + mt * 16 + lm;
                int boff = (lkh * 16 + ks * 32) ^ ((m & 7) << 4);
                uint32_t Ah[4];
                ldsm_x4(Ah, As + m * 128 + boff);
                #pragma unroll
                for (int nt = 0; nt < 8; nt++)
                    mma_f16(acc[mt][nt], Ah, &Bh[nt >> 1][(nt & 1) * 2]);
            }
        }
        __syncthreads();
    }

    int gr = lane >> 2, gc = (lane & 3) * 2;
    #pragma unroll
    for (int mt = 0; mt < 2; mt++) {
        #pragma unroll
        for (int nt = 0; nt < 8; nt++) {
            int r0 = wm * 32 + mt * 16 + gr;
            int col = N0 + wn * 64 + nt * 8 + gc;
            if (r0 < rows) {
                int tok = rowTokS[r0]; float w = rowWS[r0];
                atomicAdd(&out[(size_t)tok * HID + col],     acc[mt][nt][0] * w);
                atomicAdd(&out[(size_t)tok * HID + col + 1], acc[mt][nt][1] * w);
            }
            if (r0 + 8 < rows) {
                int tok = rowTokS[r0 + 8]; float w = rowWS[r0 + 8];
                atomicAdd(&out[(size_t)tok * HID + col],     acc[mt][nt][2] * w);
                atomicAdd(&out[(size_t)tok * HID + col + 1], acc[mt][nt][3] * w);
            }
        }
    }
}

// ===================== launch =====================
extern "C" void kernel_launch(void* const* d_in, const int* in_sizes, int n_in,
                              void* d_out, int out_size) {
    const float* x    = (const float*)d_in[0];
    const float* rw   = (const float*)d_in[1];
    const float* bias = (const float*)d_in[2];
    const float* wg   = (const float*)d_in[3];
    const float* wu   = (const float*)d_in[4];
    const float* wd   = (const float*)d_in[5];
    const float* swg  = (const float*)d_in[6];
    const float* swu  = (const float*)d_in[7];
    const float* swd  = (const float*)d_in[8];
    float* out = (float*)d_out;

    cudaFuncSetAttribute(gu_gemm, cudaFuncAttributeMaxDynamicSharedMemorySize, GU_SMEM);
    cudaFuncSetAttribute(dn_gemm, cudaFuncAttributeMaxDynamicSharedMemorySize, DN_SMEM);

    cudaMemsetAsync(d_out, 0, (size_t)out_size * sizeof(float));
    zero_kernel<<<1, 64>>>();
    prep_x<<<1024, 256>>>(x);
    router_kernel<<<T_TOK / 8, 256>>>(x, rw, bias);
    build_tiles_kernel<<<1, 32>>>();

    gu_gemm<<<dim3(INTD / 64, MAXTILES), 256, GU_SMEM>>>(wg, wu, swg, swu);
    dn_gemm<<<dim3(HID / 128, MAXTILES), 256, DN_SMEM>>>(wd, swd, out);
}

// round 13
// speedup vs baseline: 1.4673x; 1.0348x over previous
#include <cuda_runtime.h>
#include <cuda_fp16.h>
#include <math.h>
#include <stdint.h>

#define T_TOK 2048
#define HID   2048
#define INTD  1024
#define NE    32
#define NE_TOT 33
#define TOPK  4
#define MAXTILES 128
#define BM    128
#define ROWS_MAX 10368

// ===================== device scratch =====================
__device__ int   g_cnt[NE_TOT];
__device__ int   g_tok[NE_TOT * T_TOK];
__device__ float g_w  [NE_TOT * T_TOK];
__device__ int   g_off[NE_TOT + 1];
__device__ int   g_tile_e[MAXTILES];
__device__ int   g_tile_s[MAXTILES];
__device__ int   g_ntiles;
// x as single fp16 plane (written by router)
__device__ __align__(16) __half g_xhi[(size_t)T_TOK * HID];
// intermediate h = silu(g)*u, single fp16 plane
__device__ __align__(16) __half g_hhi[(size_t)ROWS_MAX * INTD];

// ===================== PTX helpers =====================
__device__ __forceinline__ uint32_t smem_u32(const void* p) {
    uint32_t a;
    asm("{ .reg .u64 t; cvta.to.shared.u64 t, %1; cvt.u32.u64 %0, t; }" : "=r"(a) : "l"(p));
    return a;
}
__device__ __forceinline__ void ldsm_x4(uint32_t* r, uint32_t a) {
    asm volatile("ldmatrix.sync.aligned.m8n8.x4.shared.b16 {%0,%1,%2,%3}, [%4];"
                 : "=r"(r[0]), "=r"(r[1]), "=r"(r[2]), "=r"(r[3]) : "r"(a));
}
__device__ __forceinline__ void ldsm_x4_t(uint32_t* r, uint32_t a) {
    asm volatile("ldmatrix.sync.aligned.m8n8.x4.trans.shared.b16 {%0,%1,%2,%3}, [%4];"
                 : "=r"(r[0]), "=r"(r[1]), "=r"(r[2]), "=r"(r[3]) : "r"(a));
}
__device__ __forceinline__ void mma_f16(float* c, const uint32_t* a, const uint32_t* b) {
    asm volatile("mma.sync.aligned.m16n8k16.row.col.f32.f16.f16.f32 "
        "{%0,%1,%2,%3}, {%4,%5,%6,%7}, {%8,%9}, {%0,%1,%2,%3};"
        : "+f"(c[0]), "+f"(c[1]), "+f"(c[2]), "+f"(c[3])
        : "r"(a[0]), "r"(a[1]), "r"(a[2]), "r"(a[3]), "r"(b[0]), "r"(b[1]));
}
__device__ __forceinline__ uint2 cvt4h(float4 f) {
    __half2 h01 = __floats2half2_rn(f.x, f.y);
    __half2 h23 = __floats2half2_rn(f.z, f.w);
    return make_uint2(*(uint32_t*)&h01, *(uint32_t*)&h23);
}
#define CP_ASYNC16(dst, src) \
    asm volatile("cp.async.cg.shared.global [%0], [%1], 16;" \
                 :: "r"((uint32_t)(dst)), "l"(src))
#define CP_COMMIT() asm volatile("cp.async.commit_group;" ::: "memory")
#define CP_WAIT0()  asm volatile("cp.async.wait_group 0;" ::: "memory")

// ===================== small kernels =====================
__global__ void zero_kernel() {
    int t = threadIdx.x;
    if (t < NE) g_cnt[t] = 0;
    if (t == NE) g_cnt[NE] = T_TOK;
}

// router + x->fp16 plane (fused)
__global__ void __launch_bounds__(256)
router_kernel(const float* __restrict__ x,
              const float* __restrict__ rw,
              const float* __restrict__ bias) {
    __shared__ float rwS[32][65];
    __shared__ float xS[8][64];
    int warp = threadIdx.x >> 5, lane = threadIdx.x & 31;
    int t = blockIdx.x * 8 + warp;

    float acc = 0.f;
    for (int h0 = 0; h0 < HID; h0 += 64) {
        __syncthreads();
        for (int i = threadIdx.x; i < 32 * 64; i += 256) {
            int e = i >> 6, j = i & 63;
            rwS[e][j] = rw[e * HID + h0 + j];
        }
        float x0 = x[(size_t)t * HID + h0 + lane];
        float x1 = x[(size_t)t * HID + h0 + 32 + lane];
        xS[warp][lane]      = x0;
        xS[warp][lane + 32] = x1;
        // fused prep: write fp16 plane
        g_xhi[(size_t)t * HID + h0 + lane]      = __float2half_rn(x0);
        g_xhi[(size_t)t * HID + h0 + 32 + lane] = __float2half_rn(x1);
        __syncthreads();
        #pragma unroll 8
        for (int j = 0; j < 64; j++)
            acc += xS[warp][j] * rwS[lane][j];
    }
    float score = 1.f / (1.f + __expf(-acc));
    float selv  = score + bias[lane];

    int   picks[TOPK];
    float pw[TOPK];
    float wsum = 0.f;
    #pragma unroll
    for (int k = 0; k < TOPK; k++) {
        float v = selv; int idx = lane;
        #pragma unroll
        for (int o = 16; o > 0; o >>= 1) {
            float v2 = __shfl_xor_sync(0xFFFFFFFFu, v, o);
            int   i2 = __shfl_xor_sync(0xFFFFFFFFu, idx, o);
            if (v2 > v || (v2 == v && i2 < idx)) { v = v2; idx = i2; }
        }
        picks[k] = idx;
        float w = __shfl_sync(0xFFFFFFFFu, score, idx);
        pw[k] = w; wsum += w;
        if (lane == idx) selv = -INFINITY;
    }
    if (lane == 0) {
        float inv = 1.f / (wsum + 1e-20f);
        #pragma unroll
        for (int k = 0; k < TOPK; k++) {
            int e = picks[k];
            int pos = atomicAdd(&g_cnt[e], 1);
            g_tok[e * T_TOK + pos] = t;
            g_w  [e * T_TOK + pos] = pw[k] * inv;
        }
        g_tok[NE * T_TOK + t] = t;
        g_w  [NE * T_TOK + t] = 1.0f;
    }
}

__global__ void build_tiles_kernel() {
    if (threadIdx.x == 0 && blockIdx.x == 0) {
        int off = 0, nt = 0;
        for (int e = 0; e < NE_TOT; e++) {
            g_off[e] = off;
            int c = g_cnt[e];
            for (int s = 0; s < c && nt < MAXTILES; s += BM) {
                g_tile_e[nt] = e; g_tile_s[nt] = s; nt++;
            }
            off += c;
        }
        g_off[NE_TOT] = off;
        g_ntiles = nt;
    }
}

// ===================== gate+up GEMM, fp16 single-pass, cp.async A =====================
// CTA: M128 x N64 (gate AND up). A = x fp16 plane via cp.async, chunk k=64.
// stage 32KB: A 16KB (128r x 64 halves, SW128) ; Bg 8KB | Bu 8KB (64k x 64n).
// 1 sync/chunk: wait A(c) -> STS B(c) -> sync -> cp.async A(c+1) + LDG B(c+1) -> MMA(c)
#define GU_SMEM (1024 + 2 * 32768)
__global__ void __launch_bounds__(256)
gu_gemm(const float* __restrict__ wgR, const float* __restrict__ wuR,
        const float* __restrict__ wgS, const float* __restrict__ wuS) {
    extern __shared__ char sm[];
    uint32_t sa = smem_u32(sm);
    int* rowTokS = (int*)sm;

    int tilei = blockIdx.y;
    if (tilei >= g_ntiles) return;
    int e = g_tile_e[tilei], s0 = g_tile_s[tilei];
    int rows = min(BM, g_cnt[e] - s0);
    int hidbase = g_off[e] + s0;
    int N0 = blockIdx.x * 64;

    int tid = threadIdx.x, lane = tid & 31, wid = tid >> 5;
    int wm = wid & 3, wn = wid >> 2;

    if (tid < 128)
        rowTokS[tid] = g_tok[e * T_TOK + s0 + min(tid, rows - 1)];
    __syncthreads();

    const float* gptr = (e < NE) ? wgR + (size_t)e * HID * INTD : wgS;
    const float* uptr = (e < NE) ? wuR + (size_t)e * HID * INTD : wuS;

    // A: rows (tid>>3)+32i (i<4), granule aJ=tid&7 (16B)
    int aJ = tid & 7;
    int tokR[4];
    uint32_t aDst[4];
    #pragma unroll
    for (int i = 0; i < 4; i++) {
        int r = (tid >> 3) + 32 * i;
        tokR[i] = rowTokS[r];
        aDst[i] = r * 128 + ((aJ * 16) ^ ((r & 7) << 4));
    }
    // B: each matrix 64k x 64n fp32; per thread row bK=tid>>2, cols bC+16j (j<4)
    int bK = tid >> 2, bC = (tid & 3) * 4;

    float4 fg[4], fu[4];
    #pragma unroll
    for (int j = 0; j < 4; j++) {
        fg[j] = *(const float4*)&gptr[(size_t)bK * INTD + N0 + bC + 16 * j];
        fu[j] = *(const float4*)&uptr[(size_t)bK * INTD + N0 + bC + 16 * j];
    }
    // prologue: cp.async A(0) -> buf0
    {
        uint32_t As0 = sa + 1024;
        #pragma unroll
        for (int i = 0; i < 4; i++)
            CP_ASYNC16(As0 + aDst[i], &g_xhi[(size_t)tokR[i] * HID + aJ * 8]);
        CP_COMMIT();
    }

    float accG[2][4][4], accU[2][4][4];
    #pragma unroll
    for (int a = 0; a < 2; a++)
        #pragma unroll
        for (int b = 0; b < 4; b++)
            #pragma unroll
            for (int f = 0; f < 4; f++) { accG[a][b][f] = 0.f; accU[a][b][f] = 0.f; }

    const int KCH = HID / 64;
    int lm = lane & 15, lkh = lane >> 4;
    int swb = (bK & 7) << 4;

    for (int c = 0; c < KCH; c++) {
        uint32_t As = sa + 1024 + (c & 1) * 32768;
        uint32_t Bg = As + 16384;
        char* Bsm = sm + 1024 + (c & 1) * 32768 + 16384;

        CP_WAIT0();
        // STS B(c) (region last read by MMA(c-2), retired before sync(c-1))
        #pragma unroll
        for (int j = 0; j < 4; j++) {
            int nb = (bC + 16 * j) * 2;
            *(uint2*)(Bsm +        bK * 128 + (nb ^ swb)) = cvt4h(fg[j]);
            *(uint2*)(Bsm + 8192 + bK * 128 + (nb ^ swb)) = cvt4h(fu[j]);
        }
        __syncthreads();

        if (c + 1 < KCH) {
            int k0 = (c + 1) * 64;
            uint32_t Asn = sa + 1024 + ((c + 1) & 1) * 32768;
            #pragma unroll
            for (int i = 0; i < 4; i++)
                CP_ASYNC16(Asn + aDst[i], &g_xhi[(size_t)tokR[i] * HID + k0 + aJ * 8]);
            CP_COMMIT();
            #pragma unroll
            for (int j = 0; j < 4; j++) {
                fg[j] = *(const float4*)&gptr[(size_t)(k0 + bK) * INTD + N0 + bC + 16 * j];
                fu[j] = *(const float4*)&uptr[(size_t)(k0 + bK) * INTD + N0 + bC + 16 * j];
            }
        }

        #pragma unroll
        for (int ks = 0; ks < 4; ks++) {
            uint32_t Gh[2][4], Uh[2][4];
            #pragma unroll
            for (int pr = 0; pr < 2; pr++) {
                int k = ks * 16 + lm;
                int n = wn * 32 + pr * 16 + lkh * 8;
                uint32_t ad = Bg + k * 128 + ((n * 2) ^ ((k & 7) << 4));
                ldsm_x4_t(Gh[pr], ad);
                ldsm_x4_t(Uh[pr], ad + 8192);
            }
            #pragma unroll
            for (int mt = 0; mt < 2; mt++) {
                int m = wm * 32 + mt * 16 + lm;
                int boff = (lkh * 16 + ks * 32) ^ ((m & 7) << 4);
                uint32_t Ah[4];
                ldsm_x4(Ah, As + m * 128 + boff);
                #pragma unroll
                for (int nt = 0; nt < 4; nt++) {
                    mma_f16(accG[mt][nt], Ah, &Gh[nt >> 1][(nt & 1) * 2]);
                    mma_f16(accU[mt][nt], Ah, &Uh[nt >> 1][(nt & 1) * 2]);
                }
            }
        }
    }

    // epilogue: fuse locally, write single fp16 plane
    int gr = lane >> 2, gc = (lane & 3) * 2;
    #pragma unroll
    for (int mt = 0; mt < 2; mt++) {
        #pragma unroll
        for (int nt = 0; nt < 4; nt++) {
            int col = N0 + wn * 32 + nt * 8 + gc;
            #pragma unroll
            for (int p = 0; p < 2; p++) {
                int r = wm * 32 + mt * 16 + gr + p * 8;
                if (r < rows) {
                    float g0 = accG[mt][nt][2 * p], g1 = accG[mt][nt][2 * p + 1];
                    float u0 = accU[mt][nt][2 * p], u1 = accU[mt][nt][2 * p + 1];
                    float h0 = (g0 / (1.f + __expf(-g0))) * u0;
                    float h1 = (g1 / (1.f + __expf(-g1))) * u1;
                    __half2 hh(__float2half_rn(h0), __float2half_rn(h1));
                    size_t o = (size_t)(hidbase + r) * INTD + col;
                    *(uint32_t*)&g_hhi[o] = *(uint32_t*)&hh;
                }
            }
        }
    }
}

// ===================== down GEMM, fp16 single-pass, cp.async A + scatter =====================
// CTA: M128 x N128. A = h fp16 plane via cp.async, chunk k=64.
// stage 32KB: A 16KB ; B 16KB (64k x 128n fp16, 256B rows).
#define DN_SMEM (1024 + 2 * 32768)
__global__ void __launch_bounds__(256)
dn_gemm(const float* __restrict__ wdR, const float* __restrict__ wdS,
        float* __restrict__ out) {
    extern __shared__ char sm[];
    uint32_t sa = smem_u32(sm);
    int* rowTokS = (int*)sm;
    float* rowWS = (float*)(sm + 512);

    int tilei = blockIdx.y;
    if (tilei >= g_ntiles) return;
    int e = g_tile_e[tilei], s0 = g_tile_s[tilei];
    int rows = min(BM, g_cnt[e] - s0);
    int hidbase = g_off[e] + s0;
    int N0 = blockIdx.x * 128;

    int tid = threadIdx.x, lane = tid & 31, wid = tid >> 5;
    int wm = wid & 3, wn = wid >> 2;

    if (tid < 128) {
        int idx = e * T_TOK + s0 + min(tid, rows - 1);
        rowTokS[tid] = g_tok[idx];
        rowWS[tid]   = g_w[idx];
    }
    __syncthreads();

    const float* wd = (e < NE) ? wdR + (size_t)e * INTD * HID : wdS;

    int aJ = tid & 7;
    int arR[4];
    uint32_t aDst[4];
    #pragma unroll
    for (int i = 0; i < 4; i++) {
        int r = (tid >> 3) + 32 * i;
        arR[i] = hidbase + min(r, rows - 1);
        aDst[i] = r * 128 + ((aJ * 16) ^ ((r & 7) << 4));
    }
    int bK = tid >> 2, bC = (tid & 3) * 4;

    float4 fb[8];
    #pragma unroll
    for (int j = 0; j < 8; j++)
        fb[j] = *(const float4*)&wd[(size_t)bK * HID + N0 + bC + 16 * j];
    {
        uint32_t As0 = sa + 1024;
        #pragma unroll
        for (int i = 0; i < 4; i++)
            CP_ASYNC16(As0 + aDst[i], &g_hhi[(size_t)arR[i] * INTD + aJ * 8]);
        CP_COMMIT();
    }

    float acc[2][8][4];
    #pragma unroll
    for (int a = 0; a < 2; a++)
        #pragma unroll
        for (int b = 0; b < 8; b++)
            #pragma unroll
            for (int f = 0; f < 4; f++) acc[a][b][f] = 0.f;

    const int KCH = INTD / 64;
    int lm = lane & 15, lkh = lane >> 4;
    int swb = (bK & 7) << 4;

    for (int c = 0; c < KCH; c++) {
        uint32_t As = sa + 1024 + (c & 1) * 32768;
        uint32_t Bs = As + 16384;
        char* Bsm = sm + 1024 + (c & 1) * 32768 + 16384;

        CP_WAIT0();
        #pragma unroll
        for (int j = 0; j < 8; j++) {
            int nb = (bC + 16 * j) * 2;
            *(uint2*)(Bsm + bK * 256 + (nb ^ swb)) = cvt4h(fb[j]);
        }
        __syncthreads();

        if (c + 1 < KCH) {
            int k0 = (c + 1) * 64;
            uint32_t Asn = sa + 1024 + ((c + 1) & 1) * 32768;
            #pragma unroll
            for (int i = 0; i < 4; i++)
                CP_ASYNC16(Asn + aDst[i], &g_hhi[(size_t)arR[i] * INTD + k0 + aJ * 8]);
            CP_COMMIT();
            #pragma unroll
            for (int j = 0; j < 8; j++)
                fb[j] = *(const float4*)&wd[(size_t)(k0 + bK) * HID + N0 + bC + 16 * j];
        }

        #pragma unroll
        for (int ks = 0; ks < 4; ks++) {
            uint32_t Bh[4][4];
            #pragma unroll
            for (int h = 0; h < 2; h++)
                #pragma unroll
                for (int pr = 0; pr < 2; pr++) {
                    int k = ks * 16 + lm;
                    int n = wn * 64 + h * 32 + pr * 16 + lkh * 8;
                    uint32_t ad = Bs + k * 256 + ((n * 2) ^ ((k & 7) << 4));
                    ldsm_x4_t(Bh[h * 2 + pr], ad);
                }
            #pragma unroll
            for (int mt = 0; mt < 2; mt++) {
                int m = wm * 32 + mt * 16 + lm;
                int boff = (lkh * 16 + ks * 32) ^ ((m & 7) << 4);
                uint32_t Ah[4];
                ldsm_x4(Ah, As + m * 128 + boff);
                #pragma unroll
                for (int nt = 0; nt < 8; nt++)
                    mma_f16(acc[mt][nt], Ah, &Bh[nt >> 1][(nt & 1) * 2]);
            }
        }
    }

    int gr = lane >> 2, gc = (lane & 3) * 2;
    #pragma unroll
    for (int mt = 0; mt < 2; mt++) {
        #pragma unroll
        for (int nt = 0; nt < 8; nt++) {
            int r0 = wm * 32 + mt * 16 + gr;
            int col = N0 + wn * 64 + nt * 8 + gc;
            if (r0 < rows) {
                int tok = rowTokS[r0]; float w = rowWS[r0];
                atomicAdd(&out[(size_t)tok * HID + col],     acc[mt][nt][0] * w);
                atomicAdd(&out[(size_t)tok * HID + col + 1], acc[mt][nt][1] * w);
            }
            if (r0 + 8 < rows) {
                int tok = rowTokS[r0 + 8]; float w = rowWS[r0 + 8];
                atomicAdd(&out[(size_t)tok * HID + col],     acc[mt][nt][2] * w);
                atomicAdd(&out[(size_t)tok * HID + col + 1], acc[mt][nt][3] * w);
            }
        }
    }
}

// ===================== launch =====================
extern "C" void kernel_launch(void* const* d_in, const int* in_sizes, int n_in,
                              void* d_out, int out_size) {
    const float* x    = (const float*)d_in[0];
    const float* rw   = (const float*)d_in[1];
    const float* bias = (const float*)d_in[2];
    const float* wg   = (const float*)d_in[3];
    const float* wu   = (const float*)d_in[4];
    const float* wd   = (const float*)d_in[5];
    const float* swg  = (const float*)d_in[6];
    const float* swu  = (const float*)d_in[7];
    const float* swd  = (const float*)d_in[8];
    float* out = (float*)d_out;

    cudaFuncSetAttribute(gu_gemm, cudaFuncAttributeMaxDynamicSharedMemorySize, GU_SMEM);
    cudaFuncSetAttribute(dn_gemm, cudaFuncAttributeMaxDynamicSharedMemorySize, DN_SMEM);

    cudaMemsetAsync(d_out, 0, (size_t)out_size * sizeof(float));
    zero_kernel<<<1, 64>>>();
    router_kernel<<<T_TOK / 8, 256>>>(x, rw, bias);
    build_tiles_kernel<<<1, 32>>>();

    gu_gemm<<<dim3(INTD / 64, MAXTILES), 256, GU_SMEM>>>(wg, wu, swg, swu);
    dn_gemm<<<dim3(HID / 128, MAXTILES), 256, DN_SMEM>>>(wd, swd, out);
}

// round 14
// speedup vs baseline: 1.6204x; 1.1043x over previous
#include <cuda_runtime.h>
#include <cuda_fp16.h>
#include <math.h>
#include <stdint.h>

#define T_TOK 2048
#define HID   2048
#define INTD  1024
#define NE    32
#define NE_TOT 33
#define TOPK  4
#define MAXTILES 128
#define BM    128
#define ROWS_MAX 10368

// ===================== device scratch =====================
__device__ int   g_cnt[NE_TOT];
__device__ int   g_tok[NE_TOT * T_TOK];
__device__ float g_w  [NE_TOT * T_TOK];
__device__ int   g_off[NE_TOT + 1];
__device__ int   g_tile_e[MAXTILES];
__device__ int   g_tile_s[MAXTILES];
__device__ int   g_ntiles;
// x as single fp16 plane (written by router)
__device__ __align__(16) __half g_xhi[(size_t)T_TOK * HID];
// intermediate h = silu(g)*u, single fp16 plane
__device__ __align__(16) __half g_hhi[(size_t)ROWS_MAX * INTD];

// ===================== PTX helpers =====================
__device__ __forceinline__ uint32_t smem_u32(const void* p) {
    uint32_t a;
    asm("{ .reg .u64 t; cvta.to.shared.u64 t, %1; cvt.u32.u64 %0, t; }" : "=r"(a) : "l"(p));
    return a;
}
__device__ __forceinline__ void ldsm_x4(uint32_t* r, uint32_t a) {
    asm volatile("ldmatrix.sync.aligned.m8n8.x4.shared.b16 {%0,%1,%2,%3}, [%4];"
                 : "=r"(r[0]), "=r"(r[1]), "=r"(r[2]), "=r"(r[3]) : "r"(a));
}
__device__ __forceinline__ void ldsm_x4_t(uint32_t* r, uint32_t a) {
    asm volatile("ldmatrix.sync.aligned.m8n8.x4.trans.shared.b16 {%0,%1,%2,%3}, [%4];"
                 : "=r"(r[0]), "=r"(r[1]), "=r"(r[2]), "=r"(r[3]) : "r"(a));
}
__device__ __forceinline__ void mma_f16(float* c, const uint32_t* a, const uint32_t* b) {
    asm volatile("mma.sync.aligned.m16n8k16.row.col.f32.f16.f16.f32 "
        "{%0,%1,%2,%3}, {%4,%5,%6,%7}, {%8,%9}, {%0,%1,%2,%3};"
        : "+f"(c[0]), "+f"(c[1]), "+f"(c[2]), "+f"(c[3])
        : "r"(a[0]), "r"(a[1]), "r"(a[2]), "r"(a[3]), "r"(b[0]), "r"(b[1]));
}
__device__ __forceinline__ uint2 cvt4h(float4 f) {
    __half2 h01 = __floats2half2_rn(f.x, f.y);
    __half2 h23 = __floats2half2_rn(f.z, f.w);
    return make_uint2(*(uint32_t*)&h01, *(uint32_t*)&h23);
}
#define CP_ASYNC16(dst, src) \
    asm volatile("cp.async.cg.shared.global [%0], [%1], 16;" \
                 :: "r"((uint32_t)(dst)), "l"(src))
#define CP_COMMIT() asm volatile("cp.async.commit_group;" ::: "memory")
#define CP_WAIT0()  asm volatile("cp.async.wait_group 0;" ::: "memory")

// ===================== small kernels =====================
__global__ void zero_kernel() {
    int t = threadIdx.x;
    if (t < NE) g_cnt[t] = 0;
    if (t == NE) g_cnt[NE] = T_TOK;
}

// router + x->fp16 plane (fused)
__global__ void __launch_bounds__(256)
router_kernel(const float* __restrict__ x,
              const float* __restrict__ rw,
              const float* __restrict__ bias) {
    __shared__ float rwS[32][65];
    __shared__ float xS[8][64];
    int warp = threadIdx.x >> 5, lane = threadIdx.x & 31;
    int t = blockIdx.x * 8 + warp;

    float acc = 0.f;
    for (int h0 = 0; h0 < HID; h0 += 64) {
        __syncthreads();
        for (int i = threadIdx.x; i < 32 * 64; i += 256) {
            int e = i >> 6, j = i & 63;
            rwS[e][j] = rw[e * HID + h0 + j];
        }
        float x0 = x[(size_t)t * HID + h0 + lane];
        float x1 = x[(size_t)t * HID + h0 + 32 + lane];
        xS[warp][lane]      = x0;
        xS[warp][lane + 32] = x1;
        g_xhi[(size_t)t * HID + h0 + lane]      = __float2half_rn(x0);
        g_xhi[(size_t)t * HID + h0 + 32 + lane] = __float2half_rn(x1);
        __syncthreads();
        #pragma unroll 8
        for (int j = 0; j < 64; j++)
            acc += xS[warp][j] * rwS[lane][j];
    }
    float score = 1.f / (1.f + __expf(-acc));
    float selv  = score + bias[lane];

    int   picks[TOPK];
    float pw[TOPK];
    float wsum = 0.f;
    #pragma unroll
    for (int k = 0; k < TOPK; k++) {
        float v = selv; int idx = lane;
        #pragma unroll
        for (int o = 16; o > 0; o >>= 1) {
            float v2 = __shfl_xor_sync(0xFFFFFFFFu, v, o);
            int   i2 = __shfl_xor_sync(0xFFFFFFFFu, idx, o);
            if (v2 > v || (v2 == v && i2 < idx)) { v = v2; idx = i2; }
        }
        picks[k] = idx;
        float w = __shfl_sync(0xFFFFFFFFu, score, idx);
        pw[k] = w; wsum += w;
        if (lane == idx) selv = -INFINITY;
    }
    if (lane == 0) {
        float inv = 1.f / (wsum + 1e-20f);
        #pragma unroll
        for (int k = 0; k < TOPK; k++) {
            int e = picks[k];
            int pos = atomicAdd(&g_cnt[e], 1);
            g_tok[e * T_TOK + pos] = t;
            g_w  [e * T_TOK + pos] = pw[k] * inv;
        }
        g_tok[NE * T_TOK + t] = t;
        g_w  [NE * T_TOK + t] = 1.0f;
    }
}

__global__ void build_tiles_kernel() {
    if (threadIdx.x == 0 && blockIdx.x == 0) {
        int off = 0, nt = 0;
        for (int e = 0; e < NE_TOT; e++) {
            g_off[e] = off;
            int c = g_cnt[e];
            for (int s = 0; s < c && nt < MAXTILES; s += BM) {
                g_tile_e[nt] = e; g_tile_s[nt] = s; nt++;
            }
            off += c;
        }
        g_off[NE_TOT] = off;
        g_ntiles = nt;
    }
}

// ===================== gate+up GEMM, fp16 single-pass, occ 2 =====================
// CTA: M128 x N64 (gate AND up). A via cp.async (fp16 plane); B inline LDG->cvt->STS
// (latency covered by sibling CTA). stage 32KB: A 16KB ; Bg 8KB | Bu 8KB.
#define GU_SMEM (1024 + 2 * 32768)
__global__ void __launch_bounds__(256, 2)
gu_gemm(const float* __restrict__ wgR, const float* __restrict__ wuR,
        const float* __restrict__ wgS, const float* __restrict__ wuS) {
    extern __shared__ char sm[];
    uint32_t sa = smem_u32(sm);
    int* rowTokS = (int*)sm;

    int tilei = blockIdx.y;
    if (tilei >= g_ntiles) return;
    int e = g_tile_e[tilei], s0 = g_tile_s[tilei];
    int rows = min(BM, g_cnt[e] - s0);
    int hidbase = g_off[e] + s0;
    int N0 = blockIdx.x * 64;

    int tid = threadIdx.x, lane = tid & 31, wid = tid >> 5;
    int wm = wid & 3, wn = wid >> 2;

    if (tid < 128)
        rowTokS[tid] = g_tok[e * T_TOK + s0 + min(tid, rows - 1)];
    __syncthreads();

    const float* gptr = (e < NE) ? wgR + (size_t)e * HID * INTD : wgS;
    const float* uptr = (e < NE) ? wuR + (size_t)e * HID * INTD : wuS;

    // A: rows (tid>>3)+32i (i<4), granule aJ=tid&7 (16B)
    int aJ = tid & 7;
    int tokR[4];
    uint32_t aDst[4];
    #pragma unroll
    for (int i = 0; i < 4; i++) {
        int r = (tid >> 3) + 32 * i;
        tokR[i] = rowTokS[r];
        aDst[i] = r * 128 + ((aJ * 16) ^ ((r & 7) << 4));
    }
    // B: each matrix 64k x 64n fp32; per thread row bK=tid>>2, cols bC+16j (j<4)
    int bK = tid >> 2, bC = (tid & 3) * 4;

    // prologue: cp.async A(0) -> buf0
    {
        uint32_t As0 = sa + 1024;
        #pragma unroll
        for (int i = 0; i < 4; i++)
            CP_ASYNC16(As0 + aDst[i], &g_xhi[(size_t)tokR[i] * HID + aJ * 8]);
        CP_COMMIT();
    }

    float accG[2][4][4], accU[2][4][4];
    #pragma unroll
    for (int a = 0; a < 2; a++)
        #pragma unroll
        for (int b = 0; b < 4; b++)
            #pragma unroll
            for (int f = 0; f < 4; f++) { accG[a][b][f] = 0.f; accU[a][b][f] = 0.f; }

    const int KCH = HID / 64;
    int lm = lane & 15, lkh = lane >> 4;
    int swb = (bK & 7) << 4;

    for (int c = 0; c < KCH; c++) {
        uint32_t As = sa + 1024 + (c & 1) * 32768;
        uint32_t Bg = As + 16384;
        char* Bsm = sm + 1024 + (c & 1) * 32768 + 16384;
        int k0 = c * 64;

        CP_WAIT0();
        // inline B(c): LDG fp32 -> cvt -> STS (exposed latency; sibling CTA covers)
        #pragma unroll
        for (int j = 0; j < 4; j++) {
            float4 g4 = *(const float4*)&gptr[(size_t)(k0 + bK) * INTD + N0 + bC + 16 * j];
            float4 u4 = *(const float4*)&uptr[(size_t)(k0 + bK) * INTD + N0 + bC + 16 * j];
            int nb = (bC + 16 * j) * 2;
            *(uint2*)(Bsm +        bK * 128 + (nb ^ swb)) = cvt4h(g4);
            *(uint2*)(Bsm + 8192 + bK * 128 + (nb ^ swb)) = cvt4h(u4);
        }
        __syncthreads();

        if (c + 1 < KCH) {
            int kn = (c + 1) * 64;
            uint32_t Asn = sa + 1024 + ((c + 1) & 1) * 32768;
            #pragma unroll
            for (int i = 0; i < 4; i++)
                CP_ASYNC16(Asn + aDst[i], &g_xhi[(size_t)tokR[i] * HID + kn + aJ * 8]);
            CP_COMMIT();
        }

        #pragma unroll
        for (int ks = 0; ks < 4; ks++) {
            uint32_t Gh[2][4], Uh[2][4];
            #pragma unroll
            for (int pr = 0; pr < 2; pr++) {
                int k = ks * 16 + lm;
                int n = wn * 32 + pr * 16 + lkh * 8;
                uint32_t ad = Bg + k * 128 + ((n * 2) ^ ((k & 7) << 4));
                ldsm_x4_t(Gh[pr], ad);
                ldsm_x4_t(Uh[pr], ad + 8192);
            }
            #pragma unroll
            for (int mt = 0; mt < 2; mt++) {
                int m = wm * 32 + mt * 16 + lm;
                int boff = (lkh * 16 + ks * 32) ^ ((m & 7) << 4);
                uint32_t Ah[4];
                ldsm_x4(Ah, As + m * 128 + boff);
                #pragma unroll
                for (int nt = 0; nt < 4; nt++) {
                    mma_f16(accG[mt][nt], Ah, &Gh[nt >> 1][(nt & 1) * 2]);
                    mma_f16(accU[mt][nt], Ah, &Uh[nt >> 1][(nt & 1) * 2]);
                }
            }
        }
    }

    // epilogue: fuse locally, write single fp16 plane
    int gr = lane >> 2, gc = (lane & 3) * 2;
    #pragma unroll
    for (int mt = 0; mt < 2; mt++) {
        #pragma unroll
        for (int nt = 0; nt < 4; nt++) {
            int col = N0 + wn * 32 + nt * 8 + gc;
            #pragma unroll
            for (int p = 0; p < 2; p++) {
                int r = wm * 32 + mt * 16 + gr + p * 8;
                if (r < rows) {
                    float g0 = accG[mt][nt][2 * p], g1 = accG[mt][nt][2 * p + 1];
                    float u0 = accU[mt][nt][2 * p], u1 = accU[mt][nt][2 * p + 1];
                    float h0 = (g0 / (1.f + __expf(-g0))) * u0;
                    float h1 = (g1 / (1.f + __expf(-g1))) * u1;
                    __half2 hh(__float2half_rn(h0), __float2half_rn(h1));
                    size_t o = (size_t)(hidbase + r) * INTD + col;
                    *(uint32_t*)&g_hhi[o] = *(uint32_t*)&hh;
                }
            }
        }
    }
}

// ===================== down GEMM, fp16 single-pass, occ 2 + scatter =====================
// CTA: M128 x N128. A via cp.async; B inline LDG->cvt->STS.
// stage 32KB: A 16KB ; B 16KB (64k x 128n fp16, 256B rows).
#define DN_SMEM (1024 + 2 * 32768)
__global__ void __launch_bounds__(256, 2)
dn_gemm(const float* __restrict__ wdR, const float* __restrict__ wdS,
        float* __restrict__ out) {
    extern __shared__ char sm[];
    uint32_t sa = smem_u32(sm);
    int* rowTokS = (int*)sm;
    float* rowWS = (float*)(sm + 512);

    int tilei = blockIdx.y;
    if (tilei >= g_ntiles) return;
    int e = g_tile_e[tilei], s0 = g_tile_s[tilei];
    int rows = min(BM, g_cnt[e] - s0);
    int hidbase = g_off[e] + s0;
    int N0 = blockIdx.x * 128;

    int tid = threadIdx.x, lane = tid & 31, wid = tid >> 5;
    int wm = wid & 3, wn = wid >> 2;

    if (tid < 128) {
        int idx = e * T_TOK + s0 + min(tid, rows - 1);
        rowTokS[tid] = g_tok[idx];
        rowWS[tid]   = g_w[idx];
    }
    __syncthreads();

    const float* wd = (e < NE) ? wdR + (size_t)e * INTD * HID : wdS;

    int aJ = tid & 7;
    int arR[4];
    uint32_t aDst[4];
    #pragma unroll
    for (int i = 0; i < 4; i++) {
        int r = (tid >> 3) + 32 * i;
        arR[i] = hidbase + min(r, rows - 1);
        aDst[i] = r * 128 + ((aJ * 16) ^ ((r & 7) << 4));
    }
    int bK = tid >> 2, bC = (tid & 3) * 4;

    {
        uint32_t As0 = sa + 1024;
        #pragma unroll
        for (int i = 0; i < 4; i++)
            CP_ASYNC16(As0 + aDst[i], &g_hhi[(size_t)arR[i] * INTD + aJ * 8]);
        CP_COMMIT();
    }

    float acc[2][8][4];
    #pragma unroll
    for (int a = 0; a < 2; a++)
        #pragma unroll
        for (int b = 0; b < 8; b++)
            #pragma unroll
            for (int f = 0; f < 4; f++) acc[a][b][f] = 0.f;

    const int KCH = INTD / 64;
    int lm = lane & 15, lkh = lane >> 4;
    int swb = (bK & 7) << 4;

    for (int c = 0; c < KCH; c++) {
        uint32_t As = sa + 1024 + (c & 1) * 32768;
        uint32_t Bs = As + 16384;
        char* Bsm = sm + 1024 + (c & 1) * 32768 + 16384;
        int k0 = c * 64;

        CP_WAIT0();
        #pragma unroll
        for (int j = 0; j < 8; j++) {
            float4 b4 = *(const float4*)&wd[(size_t)(k0 + bK) * HID + N0 + bC + 16 * j];
            int nb = (bC + 16 * j) * 2;
            *(uint2*)(Bsm + bK * 256 + (nb ^ swb)) = cvt4h(b4);
        }
        __syncthreads();

        if (c + 1 < KCH) {
            int kn = (c + 1) * 64;
            uint32_t Asn = sa + 1024 + ((c + 1) & 1) * 32768;
            #pragma unroll
            for (int i = 0; i < 4; i++)
                CP_ASYNC16(Asn + aDst[i], &g_hhi[(size_t)arR[i] * INTD + kn + aJ * 8]);
            CP_COMMIT();
        }

        #pragma unroll
        for (int ks = 0; ks < 4; ks++) {
            uint32_t Bh[4][4];
            #pragma unroll
            for (int h = 0; h < 2; h++)
                #pragma unroll
                for (int pr = 0; pr < 2; pr++) {
                    int k = ks * 16 + lm;
                    int n = wn * 64 + h * 32 + pr * 16 + lkh * 8;
                    uint32_t ad = Bs + k * 256 + ((n * 2) ^ ((k & 7) << 4));
                    ldsm_x4_t(Bh[h * 2 + pr], ad);
                }
            #pragma unroll
            for (int mt = 0; mt < 2; mt++) {
                int m = wm * 32 + mt * 16 + lm;
                int boff = (lkh * 16 + ks * 32) ^ ((m & 7) << 4);
                uint32_t Ah[4];
                ldsm_x4(Ah, As + m * 128 + boff);
                #pragma unroll
                for (int nt = 0; nt < 8; nt++)
                    mma_f16(acc[mt][nt], Ah, &Bh[nt >> 1][(nt & 1) * 2]);
            }
        }
    }

    int gr = lane >> 2, gc = (lane & 3) * 2;
    #pragma unroll
    for (int mt = 0; mt < 2; mt++) {
        #pragma unroll
        for (int nt = 0; nt < 8; nt++) {
            int r0 = wm * 32 + mt * 16 + gr;
            int col = N0 + wn * 64 + nt * 8 + gc;
            if (r0 < rows) {
                int tok = rowTokS[r0]; float w = rowWS[r0];
                atomicAdd(&out[(size_t)tok * HID + col],     acc[mt][nt][0] * w);
                atomicAdd(&out[(size_t)tok * HID + col + 1], acc[mt][nt][1] * w);
            }
            if (r0 + 8 < rows) {
                int tok = rowTokS[r0 + 8]; float w = rowWS[r0 + 8];
                atomicAdd(&out[(size_t)tok * HID + col],     acc[mt][nt][2] * w);
                atomicAdd(&out[(size_t)tok * HID + col + 1], acc[mt][nt][3] * w);
            }
        }
    }
}

// ===================== launch =====================
extern "C" void kernel_launch(void* const* d_in, const int* in_sizes, int n_in,
                              void* d_out, int out_size) {
    const float* x    = (const float*)d_in[0];
    const float* rw   = (const float*)d_in[1];
    const float* bias = (const float*)d_in[2];
    const float* wg   = (const float*)d_in[3];
    const float* wu   = (const float*)d_in[4];
    const float* wd   = (const float*)d_in[5];
    const float* swg  = (const float*)d_in[6];
    const float* swu  = (const float*)d_in[7];
    const float* swd  = (const float*)d_in[8];
    float* out = (float*)d_out;

    cudaFuncSetAttribute(gu_gemm, cudaFuncAttributeMaxDynamicSharedMemorySize, GU_SMEM);
    cudaFuncSetAttribute(dn_gemm, cudaFuncAttributeMaxDynamicSharedMemorySize, DN_SMEM);

    cudaMemsetAsync(d_out, 0, (size_t)out_size * sizeof(float));
    zero_kernel<<<1, 64>>>();
    router_kernel<<<T_TOK / 8, 256>>>(x, rw, bias);
    build_tiles_kernel<<<1, 32>>>();

    gu_gemm<<<dim3(INTD / 64, MAXTILES), 256, GU_SMEM>>>(wg, wu, swg, swu);
    dn_gemm<<<dim3(HID / 128, MAXTILES), 256, DN_SMEM>>>(wd, swd, out);
}